// round 8
// baseline (speedup 1.0000x reference)
#include <cuda_runtime.h>
#include <cuda_bf16.h>
#include <math.h>
#include <stdint.h>

#define NN 50000
#define EE 800000

// ================= scratch (device globals) =================
__device__ uint32_t g_x2[(size_t)NN * 128];    // node_features split (hi,lo u32 pairs)
__device__ uint32_t g_t2[(size_t)NN * 64];     // pre-mlp intermediate, split
__device__ uint32_t g_emb2[(size_t)NN * 256];  // [x|h1|h2|h3] split storage
__device__ float    g_yr[(size_t)NN * 128];    // per-layer [y | r] fp32
// packed weight images (ushort units):
//  pre1@0 (128x64), pre2@16384 (64x64), L0@24576 (64x128), L1@40960 (128x128), L2@73728 (192x128)
__device__ __align__(16) unsigned short g_Bp[122880];
__device__ int   g_cnt[NN];
__device__ int   g_rowptr[NN];
__device__ int   g_cursor[NN];
__device__ int   g_csr_src[EE];
__device__ float g_invdeg[NN];
__device__ int   g_part[256];
__device__ float g_s[256];

__device__ __forceinline__ void split2(float x, float y, uint32_t& hi, uint32_t& lo) {
    __nv_bfloat16 hx = __float2bfloat16(x), hy = __float2bfloat16(y);
    __nv_bfloat16 lx = __float2bfloat16(x - __bfloat162float(hx));
    __nv_bfloat16 ly = __float2bfloat16(y - __bfloat162float(hy));
    hi = ((uint32_t)__bfloat16_as_ushort(hy) << 16) | __bfloat16_as_ushort(hx);
    lo = ((uint32_t)__bfloat16_as_ushort(ly) << 16) | __bfloat16_as_ushort(lx);
}

// ================= CSR build =================
__global__ void zero_kernel() {
    int i = blockIdx.x * blockDim.x + threadIdx.x;
    if (i < NN) g_cnt[i] = 0;
}
__global__ void hist_kernel(const int* __restrict__ ei) {
    int e = blockIdx.x * blockDim.x + threadIdx.x;
    if (e < EE) atomicAdd(&g_cnt[ei[EE + e]], 1);
}
__global__ void part_kernel() {
    __shared__ int s[256];
    int t = threadIdx.x, b = blockIdx.x;
    int i = b * 256 + t;
    int v = (i < NN) ? g_cnt[i] : 0;
    s[t] = v;
    __syncthreads();
    for (int off = 128; off > 0; off >>= 1) {
        if (t < off) s[t] += s[t + off];
        __syncthreads();
    }
    if (t == 0) g_part[b] = s[0];
}
__global__ void scanp_kernel(int nb) {
    __shared__ int s[256];
    int t = threadIdx.x;
    int v = (t < nb) ? g_part[t] : 0;
    s[t] = v;
    __syncthreads();
    for (int off = 1; off < 256; off <<= 1) {
        int add = (t >= off) ? s[t - off] : 0;
        __syncthreads();
        s[t] += add;
        __syncthreads();
    }
    if (t < nb) g_part[t] = s[t] - v;  // exclusive
}
__global__ void fill_kernel() {
    __shared__ int s[256];
    int t = threadIdx.x, b = blockIdx.x;
    int i = b * 256 + t;
    int v = (i < NN) ? g_cnt[i] : 0;
    s[t] = v;
    __syncthreads();
    for (int off = 1; off < 256; off <<= 1) {
        int add = (t >= off) ? s[t - off] : 0;
        __syncthreads();
        s[t] += add;
        __syncthreads();
    }
    if (i < NN) {
        int base = g_part[b] + s[t] - v;
        g_rowptr[i] = base;
        g_cursor[i] = base;
        g_invdeg[i] = 1.0f / (float)(v > 1 ? v : 1);
    }
}
__global__ void scatter_kernel(const int* __restrict__ ei) {
    int e = blockIdx.x * blockDim.x + threadIdx.x;
    if (e < EE) {
        int dst = ei[EE + e];
        int pos = atomicAdd(&g_cursor[dst], 1);
        g_csr_src[pos] = ei[e];
    }
}

// ================= convert node_features to split storage =================
__global__ void convertX_kernel(const float* __restrict__ X) {
    int idx = blockIdx.x * blockDim.x + threadIdx.x;
    if (idx >= NN * 64) return;
    int row = idx >> 6, j = idx & 63;
    float2 v = *(const float2*)&X[(size_t)row * 128 + 2 * j];
    uint32_t hi, lo;
    split2(v.x, v.y, hi, lo);
    *(uint2*)&g_x2[(size_t)row * 128 + 2 * j] = make_uint2(hi, lo);
}

// ================= pack ALL weight images + zero g_s =================
__device__ __forceinline__ void pack_one(float w, int k, int n, int NTILE, int off_us) {
    int kc = k >> 4, kin = k & 15, nc = n >> 3, nin = n & 7;
    int lane = nin * 4 + ((kin & 7) >> 1);
    int reg = kin >> 3, half = kin & 1;
    int base = ((kc * (NTILE >> 3) + nc) * 32 + lane) * 4;  // u32 idx of frag
    __nv_bfloat16 hi = __float2bfloat16(w);
    __nv_bfloat16 lo = __float2bfloat16(w - __bfloat162float(hi));
    g_Bp[off_us + (base + reg) * 2 + half]     = __bfloat16_as_ushort(hi);
    g_Bp[off_us + (base + 2 + reg) * 2 + half] = __bfloat16_as_ushort(lo);
}
__global__ void packAll_kernel(const float* __restrict__ pre_w1, const float* __restrict__ pre_w2,
                               const float* __restrict__ wl0, const float* __restrict__ wr0,
                               const float* __restrict__ wl1, const float* __restrict__ wr1,
                               const float* __restrict__ wl2, const float* __restrict__ wr2,
                               const float* __restrict__ skip) {
    int idx = blockIdx.x * blockDim.x + threadIdx.x;
    if (idx < 256) g_s[idx] = 0.f;
    if (idx < 8192) {  // pre1: K=128, N=64
        int k = idx >> 6, n = idx & 63;
        pack_one(pre_w1[k * 64 + n], k, n, 64, 0);
    } else if (idx < 12288) {  // pre2: K=64, N=64
        int j = idx - 8192;
        int k = j >> 6, n = j & 63;
        pack_one(pre_w2[k * 64 + n], k, n, 64, 16384);
    } else if (idx < 20480) {  // L0: K=64, N=128
        int j = idx - 12288;
        int k = j >> 7, n = j & 127;
        float g = 1.f / (1.f + expf(-skip[0]));
        float w = ((n < 64) ? wl0[k * 64 + n] : wr0[k * 64 + (n - 64)]) * g;
        pack_one(w, k, n, 128, 24576);
    } else if (idx < 36864) {  // L1: K=128, N=128
        int j = idx - 20480;
        int k = j >> 7, n = j & 127;
        float g = 1.f / (1.f + expf(-skip[3 + (k >> 6)]));
        float w = ((n < 64) ? wl1[k * 64 + n] : wr1[k * 64 + (n - 64)]) * g;
        pack_one(w, k, n, 128, 40960);
    } else if (idx < 61440) {  // L2: K=192, N=128
        int j = idx - 36864;
        int k = j >> 7, n = j & 127;
        float g = 1.f / (1.f + expf(-skip[6 + (k >> 6)]));
        float w = ((n < 64) ? wl2[k * 64 + n] : wr2[k * 64 + (n - 64)]) * g;
        pack_one(w, k, n, 128, 73728);
    }
}

// ================= HMMA GEMM, 2-D warp tiling (32 rows x NTILE/2 cols / warp) ====
__device__ __forceinline__ void mma16816(float* acc, const uint32_t* a,
                                         uint32_t b0, uint32_t b1) {
    asm volatile(
        "mma.sync.aligned.m16n8k16.row.col.f32.bf16.bf16.f32 "
        "{%0,%1,%2,%3}, {%4,%5,%6,%7}, {%8,%9}, {%0,%1,%2,%3};"
        : "+f"(acc[0]), "+f"(acc[1]), "+f"(acc[2]), "+f"(acc[3])
        : "r"(a[0]), "r"(a[1]), "r"(a[2]), "r"(a[3]), "r"(b0), "r"(b1));
}

template <int NTILE, int OUTSPLIT, int COLSUM>
__global__ void __launch_bounds__(256) mma_gemm3(
    const uint32_t* __restrict__ A2, int ldu, int K,
    const uint4* __restrict__ Bp,
    const float* __restrict__ bias, int act,
    void* __restrict__ Cout, int ldc, int M) {
    constexpr int NFRAG = NTILE / 8;
    constexpr int WNF = NFRAG / 2;   // N-frags per warp
    const int tid = threadIdx.x;
    const int wid = tid >> 5, lane = tid & 31;
    const int wm = wid >> 1, wn = wid & 1;  // 4 M-warps x 2 N-warps
    const int q = lane & 3, tq = lane >> 2;
    const int rb = blockIdx.x * 128 + wm * 32 + tq;

    float acc[2][WNF][4];
#pragma unroll
    for (int m = 0; m < 2; m++)
#pragma unroll
        for (int i = 0; i < WNF; i++)
#pragma unroll
            for (int j = 0; j < 4; j++) acc[m][i][j] = 0.f;

    for (int kc = 0; kc < K / 16; kc++) {
        const int c0 = kc * 16 + 2 * q;
        uint32_t ah[2][4], al[2][4];
#pragma unroll
        for (int mf = 0; mf < 2; mf++) {
            int ra = rb + mf * 16, rc = ra + 8;
            uint2 p00 = make_uint2(0u, 0u), p01 = p00, p10 = p00, p11 = p00;
            if (ra < M) {
                p00 = *(const uint2*)&A2[(size_t)ra * ldu + c0];
                p01 = *(const uint2*)&A2[(size_t)ra * ldu + c0 + 8];
            }
            if (rc < M) {
                p10 = *(const uint2*)&A2[(size_t)rc * ldu + c0];
                p11 = *(const uint2*)&A2[(size_t)rc * ldu + c0 + 8];
            }
            ah[mf][0] = p00.x; ah[mf][1] = p10.x; ah[mf][2] = p01.x; ah[mf][3] = p11.x;
            al[mf][0] = p00.y; al[mf][1] = p10.y; al[mf][2] = p01.y; al[mf][3] = p11.y;
        }
        const uint4* bp = Bp + (size_t)(kc * NFRAG + wn * WNF) * 32 + lane;
#pragma unroll
        for (int nc = 0; nc < WNF; nc++) {
            uint4 b = bp[nc * 32];
            mma16816(acc[0][nc], ah[0], b.x, b.y);
            mma16816(acc[0][nc], ah[0], b.z, b.w);
            mma16816(acc[0][nc], al[0], b.x, b.y);
            mma16816(acc[1][nc], ah[1], b.x, b.y);
            mma16816(acc[1][nc], ah[1], b.z, b.w);
            mma16816(acc[1][nc], al[1], b.x, b.y);
        }
    }

#pragma unroll
    for (int nc = 0; nc < WNF; nc++) {
        int col = wn * (NTILE / 2) + nc * 8 + 2 * q;
        float b0v = bias ? bias[col] : 0.f;
        float b1v = bias ? bias[col + 1] : 0.f;
        float cs0 = 0.f, cs1 = 0.f;
#pragma unroll
        for (int mf = 0; mf < 2; mf++) {
            int ra = rb + mf * 16, rc = ra + 8;
            float x0 = acc[mf][nc][0] + b0v, y0 = acc[mf][nc][1] + b1v;
            float x1 = acc[mf][nc][2] + b0v, y1 = acc[mf][nc][3] + b1v;
            if (act) {
                x0 = fmaxf(x0, 0.f); y0 = fmaxf(y0, 0.f);
                x1 = fmaxf(x1, 0.f); y1 = fmaxf(y1, 0.f);
            }
            if (OUTSPLIT) {
                uint32_t* Cu = (uint32_t*)Cout;
                uint32_t hi, lo;
                if (ra < M) {
                    split2(x0, y0, hi, lo);
                    *(uint2*)&Cu[(size_t)ra * ldc + col] = make_uint2(hi, lo);
                }
                if (rc < M) {
                    split2(x1, y1, hi, lo);
                    *(uint2*)&Cu[(size_t)rc * ldc + col] = make_uint2(hi, lo);
                }
            } else {
                float* Cf = (float*)Cout;
                if (ra < M) *(float2*)&Cf[(size_t)ra * ldc + col] = make_float2(x0, y0);
                if (rc < M) *(float2*)&Cf[(size_t)rc * ldc + col] = make_float2(x1, y1);
            }
            if (COLSUM) {
                if (ra < M) { cs0 += x0; cs1 += y0; }
                if (rc < M) { cs0 += x1; cs1 += y1; }
            }
        }
        if (COLSUM) {
            cs0 += __shfl_down_sync(0xffffffffu, cs0, 16);
            cs1 += __shfl_down_sync(0xffffffffu, cs1, 16);
            cs0 += __shfl_down_sync(0xffffffffu, cs0, 8);
            cs1 += __shfl_down_sync(0xffffffffu, cs1, 8);
            cs0 += __shfl_down_sync(0xffffffffu, cs0, 4);
            cs1 += __shfl_down_sync(0xffffffffu, cs1, 4);
            if (tq == 0) {
                atomicAdd(&g_s[col], cs0);
                atomicAdd(&g_s[col + 1], cs1);
            }
        }
    }
}

// ================= aggregation: one warp per node + running colsum ============
__global__ void agg_kernel(const float* __restrict__ bl, int outcol) {
    __shared__ float2 sh[8][32];
    int wid = threadIdx.x >> 5;
    int lane = threadIdx.x & 31;
    int n = blockIdx.x * 8 + wid;  // grid 6250 x 8 warps = exactly NN
    const int beg = g_rowptr[n], cnt = g_cnt[n];
    const float* __restrict__ yr = g_yr;
    float sx = 0.f, sy = 0.f;
    for (int k = 0; k < cnt; k++) {
        int src = g_csr_src[beg + k];
        float2 v = *reinterpret_cast<const float2*>(&yr[(size_t)src * 128 + 2 * lane]);
        sx += v.x;
        sy += v.y;
    }
    float inv = g_invdeg[n];
    float2 r = *reinterpret_cast<const float2*>(&yr[(size_t)n * 128 + 64 + 2 * lane]);
    float h0 = fmaxf(sx * inv + bl[2 * lane] + r.x, 0.f);
    float h1 = fmaxf(sy * inv + bl[2 * lane + 1] + r.y, 0.f);
    uint32_t hi, lo;
    split2(h0, h1, hi, lo);
    *(uint2*)&g_emb2[(size_t)n * 256 + outcol + 2 * lane] = make_uint2(hi, lo);

    sh[wid][lane] = make_float2(h0, h1);
    __syncthreads();
    if (wid == 0) {
        float s0 = 0.f, s1 = 0.f;
#pragma unroll
        for (int w = 0; w < 8; w++) {
            float2 v = sh[w][lane];
            s0 += v.x;
            s1 += v.y;
        }
        atomicAdd(&g_s[outcol + 2 * lane], s0);
        atomicAdd(&g_s[outcol + 2 * lane + 1], s1);
    }
}

// ================= post mlp =================
__global__ void post_kernel(const float* __restrict__ w1, const float* __restrict__ b1,
                            const float* __restrict__ w2, const float* __restrict__ b2,
                            const float* __restrict__ w3, const float* __restrict__ b3,
                            const float* __restrict__ w4, const float* __restrict__ b4,
                            float* __restrict__ out) {
    __shared__ float s1[64], s2[64], s3[256];
    int t = threadIdx.x;
    if (t < 64) {
        float a = b1[t];
        for (int k = 0; k < 256; k++) a += g_s[k] * w1[k * 64 + t];
        s1[t] = (a > 0.f) ? a : 0.1f * a;
    }
    __syncthreads();
    if (t < 64) {
        float a = b2[t];
        for (int k = 0; k < 64; k++) a += s1[k] * w2[k * 64 + t];
        s2[t] = fmaxf(a, 0.f);
    }
    __syncthreads();
    {
        float a = b3[t];
        for (int k = 0; k < 64; k++) a += s2[k] * w3[k * 256 + t];
        s3[t] = fmaxf(a, 0.f);
    }
    __syncthreads();
    if (t < 64) {
        float a = b4[t];
        for (int k = 0; k < 256; k++) a += s3[k] * w4[k * 64 + t];
        out[t] = a;
    }
}

// ================= launch =================
extern "C" void kernel_launch(void* const* d_in, const int* in_sizes, int n_in,
                              void* d_out, int out_size) {
    const float* node_features = (const float*)d_in[0];
    const int*   edge_index    = (const int*)d_in[1];
    const float* pre_w1 = (const float*)d_in[2];
    const float* pre_b1 = (const float*)d_in[3];
    const float* pre_w2 = (const float*)d_in[4];
    const float* pre_b2 = (const float*)d_in[5];
    const float* skip   = (const float*)d_in[6];
    const float* wl[3] = {(const float*)d_in[7], (const float*)d_in[10], (const float*)d_in[13]};
    const float* bl[3] = {(const float*)d_in[8], (const float*)d_in[11], (const float*)d_in[14]};
    const float* wr[3] = {(const float*)d_in[9], (const float*)d_in[12], (const float*)d_in[15]};
    const float* post_w1 = (const float*)d_in[16];
    const float* post_b1 = (const float*)d_in[17];
    const float* post_w2 = (const float*)d_in[18];
    const float* post_b2 = (const float*)d_in[19];
    const float* post_w3 = (const float*)d_in[20];
    const float* post_b3 = (const float*)d_in[21];
    const float* post_w4 = (const float*)d_in[22];
    const float* post_b4 = (const float*)d_in[23];
    float* out = (float*)d_out;

    uint32_t *p_x2, *p_t2, *p_emb2;
    float* p_yr;
    unsigned short* p_Bp;
    cudaGetSymbolAddress((void**)&p_x2, g_x2);
    cudaGetSymbolAddress((void**)&p_t2, g_t2);
    cudaGetSymbolAddress((void**)&p_emb2, g_emb2);
    cudaGetSymbolAddress((void**)&p_yr, g_yr);
    cudaGetSymbolAddress((void**)&p_Bp, g_Bp);

    const int NB = (NN + 255) / 256;  // 196
    const int MB = (NN + 127) / 128;  // 391

    cudaStream_t s2;
    cudaStreamCreateWithFlags(&s2, cudaStreamNonBlocking);
    cudaEvent_t eFork, eJoin;
    cudaEventCreateWithFlags(&eFork, cudaEventDisableTiming);
    cudaEventCreateWithFlags(&eJoin, cudaEventDisableTiming);

    cudaEventRecord(eFork, 0);
    cudaStreamWaitEvent(s2, eFork, 0);

    // --- side stream: CSR build ---
    zero_kernel<<<NB, 256, 0, s2>>>();
    hist_kernel<<<(EE + 255) / 256, 256, 0, s2>>>(edge_index);
    part_kernel<<<NB, 256, 0, s2>>>();
    scanp_kernel<<<1, 256, 0, s2>>>(NB);
    fill_kernel<<<NB, 256, 0, s2>>>();
    scatter_kernel<<<(EE + 255) / 256, 256, 0, s2>>>(edge_index);
    cudaEventRecord(eJoin, s2);

    // --- main stream: convert + pack + pre-MLP GEMMs ---
    convertX_kernel<<<(NN * 64 + 255) / 256, 256>>>(node_features);
    packAll_kernel<<<(61440 + 255) / 256, 256>>>(pre_w1, pre_w2, wl[0], wr[0], wl[1], wr[1],
                                                 wl[2], wr[2], skip);
    mma_gemm3<64, 1, 0><<<MB, 256>>>(p_x2, 128, 128, (const uint4*)(p_Bp), pre_b1, 1,
                                     p_t2, 64, NN);
    mma_gemm3<64, 1, 1><<<MB, 256>>>(p_t2, 64, 64, (const uint4*)(p_Bp + 16384), pre_b2, 0,
                                     p_emb2, 256, NN);
    mma_gemm3<128, 0, 0><<<MB, 256>>>(p_emb2, 256, 64, (const uint4*)(p_Bp + 24576),
                                      (const float*)nullptr, 0, p_yr, 128, NN);

    cudaStreamWaitEvent(0, eJoin, 0);
    agg_kernel<<<NN / 8, 256>>>(bl[0], 64);

    mma_gemm3<128, 0, 0><<<MB, 256>>>(p_emb2, 256, 128, (const uint4*)(p_Bp + 40960),
                                      (const float*)nullptr, 0, p_yr, 128, NN);
    agg_kernel<<<NN / 8, 256>>>(bl[1], 128);

    mma_gemm3<128, 0, 0><<<MB, 256>>>(p_emb2, 256, 192, (const uint4*)(p_Bp + 73728),
                                      (const float*)nullptr, 0, p_yr, 128, NN);
    agg_kernel<<<NN / 8, 256>>>(bl[2], 192);

    post_kernel<<<1, 256>>>(post_w1, post_b1, post_w2, post_b2, post_w3, post_b3,
                            post_w4, post_b4, out);

    cudaEventDestroy(eFork);
    cudaEventDestroy(eJoin);
    cudaStreamDestroy(s2);
}

// round 9
// speedup vs baseline: 1.5119x; 1.5119x over previous
#include <cuda_runtime.h>
#include <cuda_bf16.h>
#include <math.h>
#include <stdint.h>

#define NN 50000
#define EE 800000

// ================= scratch (device globals) =================
__device__ uint32_t g_x2[(size_t)NN * 128];    // node_features split (hi,lo u32 pairs)
__device__ uint32_t g_t2[(size_t)NN * 64];     // pre-mlp intermediate, split
__device__ uint32_t g_emb2[(size_t)NN * 256];  // [x|h1|h2|h3] split storage
__device__ float    g_yr[(size_t)NN * 128];    // per-layer [y | r] fp32
// packed weight images (ushort units):
//  pre1@0 (128x64), pre2@16384 (64x64), L0@24576 (64x128), L1@40960 (128x128), L2@73728 (192x128)
__device__ __align__(16) unsigned short g_Bp[122880];
__device__ int   g_cnt[NN];
__device__ int   g_rowptr[NN];
__device__ int   g_cursor[NN];
__device__ int   g_csr_src[EE];
__device__ float g_invdeg[NN];
__device__ int   g_part[256];
__device__ float g_s[256];

__device__ __forceinline__ void split2(float x, float y, uint32_t& hi, uint32_t& lo) {
    __nv_bfloat16 hx = __float2bfloat16(x), hy = __float2bfloat16(y);
    __nv_bfloat16 lx = __float2bfloat16(x - __bfloat162float(hx));
    __nv_bfloat16 ly = __float2bfloat16(y - __bfloat162float(hy));
    hi = ((uint32_t)__bfloat16_as_ushort(hy) << 16) | __bfloat16_as_ushort(hx);
    lo = ((uint32_t)__bfloat16_as_ushort(ly) << 16) | __bfloat16_as_ushort(lx);
}

// ================= CSR build =================
__global__ void zero_kernel() {
    int i = blockIdx.x * blockDim.x + threadIdx.x;
    if (i < NN) g_cnt[i] = 0;
    if (i < 256) g_s[i] = 0.f;
}
__global__ void hist_kernel(const int* __restrict__ ei) {
    int e = blockIdx.x * blockDim.x + threadIdx.x;
    if (e < EE) atomicAdd(&g_cnt[ei[EE + e]], 1);
}
__global__ void part_kernel() {
    __shared__ int s[256];
    int t = threadIdx.x, b = blockIdx.x;
    int i = b * 256 + t;
    int v = (i < NN) ? g_cnt[i] : 0;
    s[t] = v;
    __syncthreads();
    for (int off = 128; off > 0; off >>= 1) {
        if (t < off) s[t] += s[t + off];
        __syncthreads();
    }
    if (t == 0) g_part[b] = s[0];
}
__global__ void scanp_kernel(int nb) {
    __shared__ int s[256];
    int t = threadIdx.x;
    int v = (t < nb) ? g_part[t] : 0;
    s[t] = v;
    __syncthreads();
    for (int off = 1; off < 256; off <<= 1) {
        int add = (t >= off) ? s[t - off] : 0;
        __syncthreads();
        s[t] += add;
        __syncthreads();
    }
    if (t < nb) g_part[t] = s[t] - v;  // exclusive
}
__global__ void fill_kernel() {
    __shared__ int s[256];
    int t = threadIdx.x, b = blockIdx.x;
    int i = b * 256 + t;
    int v = (i < NN) ? g_cnt[i] : 0;
    s[t] = v;
    __syncthreads();
    for (int off = 1; off < 256; off <<= 1) {
        int add = (t >= off) ? s[t - off] : 0;
        __syncthreads();
        s[t] += add;
        __syncthreads();
    }
    if (i < NN) {
        int base = g_part[b] + s[t] - v;
        g_rowptr[i] = base;
        g_cursor[i] = base;
        g_invdeg[i] = 1.0f / (float)(v > 1 ? v : 1);
    }
}
__global__ void scatter_kernel(const int* __restrict__ ei) {
    int e = blockIdx.x * blockDim.x + threadIdx.x;
    if (e < EE) {
        int dst = ei[EE + e];
        int pos = atomicAdd(&g_cursor[dst], 1);
        g_csr_src[pos] = ei[e];
    }
}

// ================= convert node_features to split storage =================
__global__ void convertX_kernel(const float* __restrict__ X) {
    int idx = blockIdx.x * blockDim.x + threadIdx.x;
    if (idx >= NN * 64) return;
    int row = idx >> 6, j = idx & 63;
    float2 v = *(const float2*)&X[(size_t)row * 128 + 2 * j];
    uint32_t hi, lo;
    split2(v.x, v.y, hi, lo);
    *(uint2*)&g_x2[(size_t)row * 128 + 2 * j] = make_uint2(hi, lo);
}

// ================= pack ALL weight images in one launch =================
__device__ __forceinline__ void pack_one(float w, int k, int n, int NTILE, int off_us) {
    int kc = k >> 4, kin = k & 15, nc = n >> 3, nin = n & 7;
    int lane = nin * 4 + ((kin & 7) >> 1);
    int reg = kin >> 3, half = kin & 1;
    int base = ((kc * (NTILE >> 3) + nc) * 32 + lane) * 4;  // u32 idx of frag
    __nv_bfloat16 hi = __float2bfloat16(w);
    __nv_bfloat16 lo = __float2bfloat16(w - __bfloat162float(hi));
    g_Bp[off_us + (base + reg) * 2 + half]     = __bfloat16_as_ushort(hi);
    g_Bp[off_us + (base + 2 + reg) * 2 + half] = __bfloat16_as_ushort(lo);
}
__global__ void packAll_kernel(const float* __restrict__ pre_w1, const float* __restrict__ pre_w2,
                               const float* __restrict__ wl0, const float* __restrict__ wr0,
                               const float* __restrict__ wl1, const float* __restrict__ wr1,
                               const float* __restrict__ wl2, const float* __restrict__ wr2,
                               const float* __restrict__ skip) {
    int idx = blockIdx.x * blockDim.x + threadIdx.x;
    if (idx < 8192) {  // pre1: K=128, N=64
        int k = idx >> 6, n = idx & 63;
        pack_one(pre_w1[k * 64 + n], k, n, 64, 0);
    } else if (idx < 12288) {  // pre2: K=64, N=64
        int j = idx - 8192;
        int k = j >> 6, n = j & 63;
        pack_one(pre_w2[k * 64 + n], k, n, 64, 16384);
    } else if (idx < 20480) {  // L0: K=64, N=128
        int j = idx - 12288;
        int k = j >> 7, n = j & 127;
        float g = 1.f / (1.f + expf(-skip[0]));
        float w = ((n < 64) ? wl0[k * 64 + n] : wr0[k * 64 + (n - 64)]) * g;
        pack_one(w, k, n, 128, 24576);
    } else if (idx < 36864) {  // L1: K=128, N=128
        int j = idx - 20480;
        int k = j >> 7, n = j & 127;
        float g = 1.f / (1.f + expf(-skip[3 + (k >> 6)]));
        float w = ((n < 64) ? wl1[k * 64 + n] : wr1[k * 64 + (n - 64)]) * g;
        pack_one(w, k, n, 128, 40960);
    } else if (idx < 61440) {  // L2: K=192, N=128
        int j = idx - 36864;
        int k = j >> 7, n = j & 127;
        float g = 1.f / (1.f + expf(-skip[6 + (k >> 6)]));
        float w = ((n < 64) ? wl2[k * 64 + n] : wr2[k * 64 + (n - 64)]) * g;
        pack_one(w, k, n, 128, 73728);
    }
}

// ================= HMMA GEMM, 2-D warp tiling (32 rows x NTILE/2 cols / warp) ====
__device__ __forceinline__ void mma16816(float* acc, const uint32_t* a,
                                         uint32_t b0, uint32_t b1) {
    asm volatile(
        "mma.sync.aligned.m16n8k16.row.col.f32.bf16.bf16.f32 "
        "{%0,%1,%2,%3}, {%4,%5,%6,%7}, {%8,%9}, {%0,%1,%2,%3};"
        : "+f"(acc[0]), "+f"(acc[1]), "+f"(acc[2]), "+f"(acc[3])
        : "r"(a[0]), "r"(a[1]), "r"(a[2]), "r"(a[3]), "r"(b0), "r"(b1));
}

template <int NTILE, int OUTSPLIT>
__global__ void __launch_bounds__(256) mma_gemm3(
    const uint32_t* __restrict__ A2, int ldu, int K,
    const uint4* __restrict__ Bp,
    const float* __restrict__ bias, int act,
    void* __restrict__ Cout, int ldc, int M) {
    constexpr int NFRAG = NTILE / 8;
    constexpr int WNF = NFRAG / 2;   // N-frags per warp
    const int tid = threadIdx.x;
    const int wid = tid >> 5, lane = tid & 31;
    const int wm = wid >> 1, wn = wid & 1;  // 4 M-warps x 2 N-warps
    const int q = lane & 3, tq = lane >> 2;
    const int rb = blockIdx.x * 128 + wm * 32 + tq;

    float acc[2][WNF][4];
#pragma unroll
    for (int m = 0; m < 2; m++)
#pragma unroll
        for (int i = 0; i < WNF; i++)
#pragma unroll
            for (int j = 0; j < 4; j++) acc[m][i][j] = 0.f;

    for (int kc = 0; kc < K / 16; kc++) {
        const int c0 = kc * 16 + 2 * q;
        uint32_t ah[2][4], al[2][4];
#pragma unroll
        for (int mf = 0; mf < 2; mf++) {
            int ra = rb + mf * 16, rc = ra + 8;
            uint2 p00 = make_uint2(0u, 0u), p01 = p00, p10 = p00, p11 = p00;
            if (ra < M) {
                p00 = *(const uint2*)&A2[(size_t)ra * ldu + c0];
                p01 = *(const uint2*)&A2[(size_t)ra * ldu + c0 + 8];
            }
            if (rc < M) {
                p10 = *(const uint2*)&A2[(size_t)rc * ldu + c0];
                p11 = *(const uint2*)&A2[(size_t)rc * ldu + c0 + 8];
            }
            ah[mf][0] = p00.x; ah[mf][1] = p10.x; ah[mf][2] = p01.x; ah[mf][3] = p11.x;
            al[mf][0] = p00.y; al[mf][1] = p10.y; al[mf][2] = p01.y; al[mf][3] = p11.y;
        }
        const uint4* bp = Bp + (size_t)(kc * NFRAG + wn * WNF) * 32 + lane;
#pragma unroll
        for (int nc = 0; nc < WNF; nc++) {
            uint4 b = bp[nc * 32];
            mma16816(acc[0][nc], ah[0], b.x, b.y);
            mma16816(acc[0][nc], ah[0], b.z, b.w);
            mma16816(acc[0][nc], al[0], b.x, b.y);
            mma16816(acc[1][nc], ah[1], b.x, b.y);
            mma16816(acc[1][nc], ah[1], b.z, b.w);
            mma16816(acc[1][nc], al[1], b.x, b.y);
        }
    }

#pragma unroll
    for (int nc = 0; nc < WNF; nc++) {
        int col = wn * (NTILE / 2) + nc * 8 + 2 * q;
        float b0v = bias ? bias[col] : 0.f;
        float b1v = bias ? bias[col + 1] : 0.f;
#pragma unroll
        for (int mf = 0; mf < 2; mf++) {
            int ra = rb + mf * 16, rc = ra + 8;
            float x0 = acc[mf][nc][0] + b0v, y0 = acc[mf][nc][1] + b1v;
            float x1 = acc[mf][nc][2] + b0v, y1 = acc[mf][nc][3] + b1v;
            if (act) {
                x0 = fmaxf(x0, 0.f); y0 = fmaxf(y0, 0.f);
                x1 = fmaxf(x1, 0.f); y1 = fmaxf(y1, 0.f);
            }
            if (OUTSPLIT) {
                uint32_t* Cu = (uint32_t*)Cout;
                uint32_t hi, lo;
                if (ra < M) {
                    split2(x0, y0, hi, lo);
                    *(uint2*)&Cu[(size_t)ra * ldc + col] = make_uint2(hi, lo);
                }
                if (rc < M) {
                    split2(x1, y1, hi, lo);
                    *(uint2*)&Cu[(size_t)rc * ldc + col] = make_uint2(hi, lo);
                }
            } else {
                float* Cf = (float*)Cout;
                if (ra < M) *(float2*)&Cf[(size_t)ra * ldc + col] = make_float2(x0, y0);
                if (rc < M) *(float2*)&Cf[(size_t)rc * ldc + col] = make_float2(x1, y1);
            }
        }
    }
}

// ================= aggregation: one warp per node (independent warps) ==========
__global__ void agg_kernel(const float* __restrict__ bl, int outcol) {
    int gw = (blockIdx.x * blockDim.x + threadIdx.x) >> 5;
    int lane = threadIdx.x & 31;
    if (gw >= NN) return;
    const int n = gw;
    const int beg = g_rowptr[n], cnt = g_cnt[n];
    const float* __restrict__ yr = g_yr;
    float sx = 0.f, sy = 0.f;
    for (int k = 0; k < cnt; k++) {
        int src = g_csr_src[beg + k];
        float2 v = *reinterpret_cast<const float2*>(&yr[(size_t)src * 128 + 2 * lane]);
        sx += v.x;
        sy += v.y;
    }
    float inv = g_invdeg[n];
    float2 r = *reinterpret_cast<const float2*>(&yr[(size_t)n * 128 + 64 + 2 * lane]);
    float h0 = fmaxf(sx * inv + bl[2 * lane] + r.x, 0.f);
    float h1 = fmaxf(sy * inv + bl[2 * lane + 1] + r.y, 0.f);
    uint32_t hi, lo;
    split2(h0, h1, hi, lo);
    *(uint2*)&g_emb2[(size_t)n * 256 + outcol + 2 * lane] = make_uint2(hi, lo);
}

// ================= column sum over split emb + post mlp =================
__global__ void colsum_kernel() {
    int t = threadIdx.x;  // 128 threads: col pair (2t, 2t+1)
    int per = (NN + gridDim.x - 1) / gridDim.x;
    int n0 = blockIdx.x * per;
    int n1 = n0 + per;
    if (n1 > NN) n1 = NN;
    float s0 = 0.f, s1 = 0.f;
    for (int n = n0; n < n1; n++) {
        uint2 w = *(const uint2*)&g_emb2[(size_t)n * 256 + 2 * t];
        s0 += __uint_as_float(w.x << 16) + __uint_as_float(w.y << 16);
        s1 += __uint_as_float(w.x & 0xFFFF0000u) + __uint_as_float(w.y & 0xFFFF0000u);
    }
    atomicAdd(&g_s[2 * t], s0);
    atomicAdd(&g_s[2 * t + 1], s1);
}
__global__ void post_kernel(const float* __restrict__ w1, const float* __restrict__ b1,
                            const float* __restrict__ w2, const float* __restrict__ b2,
                            const float* __restrict__ w3, const float* __restrict__ b3,
                            const float* __restrict__ w4, const float* __restrict__ b4,
                            float* __restrict__ out) {
    __shared__ float s1[64], s2[64], s3[256];
    int t = threadIdx.x;
    if (t < 64) {
        float a = b1[t];
        for (int k = 0; k < 256; k++) a += g_s[k] * w1[k * 64 + t];
        s1[t] = (a > 0.f) ? a : 0.1f * a;
    }
    __syncthreads();
    if (t < 64) {
        float a = b2[t];
        for (int k = 0; k < 64; k++) a += s1[k] * w2[k * 64 + t];
        s2[t] = fmaxf(a, 0.f);
    }
    __syncthreads();
    {
        float a = b3[t];
        for (int k = 0; k < 64; k++) a += s2[k] * w3[k * 256 + t];
        s3[t] = fmaxf(a, 0.f);
    }
    __syncthreads();
    if (t < 64) {
        float a = b4[t];
        for (int k = 0; k < 256; k++) a += s3[k] * w4[k * 64 + t];
        out[t] = a;
    }
}

// ================= launch =================
extern "C" void kernel_launch(void* const* d_in, const int* in_sizes, int n_in,
                              void* d_out, int out_size) {
    const float* node_features = (const float*)d_in[0];
    const int*   edge_index    = (const int*)d_in[1];
    const float* pre_w1 = (const float*)d_in[2];
    const float* pre_b1 = (const float*)d_in[3];
    const float* pre_w2 = (const float*)d_in[4];
    const float* pre_b2 = (const float*)d_in[5];
    const float* skip   = (const float*)d_in[6];
    const float* wl[3] = {(const float*)d_in[7], (const float*)d_in[10], (const float*)d_in[13]};
    const float* bl[3] = {(const float*)d_in[8], (const float*)d_in[11], (const float*)d_in[14]};
    const float* wr[3] = {(const float*)d_in[9], (const float*)d_in[12], (const float*)d_in[15]};
    const float* post_w1 = (const float*)d_in[16];
    const float* post_b1 = (const float*)d_in[17];
    const float* post_w2 = (const float*)d_in[18];
    const float* post_b2 = (const float*)d_in[19];
    const float* post_w3 = (const float*)d_in[20];
    const float* post_b3 = (const float*)d_in[21];
    const float* post_w4 = (const float*)d_in[22];
    const float* post_b4 = (const float*)d_in[23];
    float* out = (float*)d_out;

    uint32_t *p_x2, *p_t2, *p_emb2;
    float* p_yr;
    unsigned short* p_Bp;
    cudaGetSymbolAddress((void**)&p_x2, g_x2);
    cudaGetSymbolAddress((void**)&p_t2, g_t2);
    cudaGetSymbolAddress((void**)&p_emb2, g_emb2);
    cudaGetSymbolAddress((void**)&p_yr, g_yr);
    cudaGetSymbolAddress((void**)&p_Bp, g_Bp);

    const int NB = (NN + 255) / 256;  // 196
    const int MB = (NN + 127) / 128;  // 391

    // CSR build
    zero_kernel<<<NB, 256>>>();
    hist_kernel<<<(EE + 255) / 256, 256>>>(edge_index);
    part_kernel<<<NB, 256>>>();
    scanp_kernel<<<1, 256>>>(NB);
    fill_kernel<<<NB, 256>>>();
    scatter_kernel<<<(EE + 255) / 256, 256>>>(edge_index);

    // convert + pack + pre-MLP GEMMs
    convertX_kernel<<<(NN * 64 + 255) / 256, 256>>>(node_features);
    packAll_kernel<<<(61440 + 255) / 256, 256>>>(pre_w1, pre_w2, wl[0], wr[0], wl[1], wr[1],
                                                 wl[2], wr[2], skip);
    mma_gemm3<64, 1><<<MB, 256>>>(p_x2, 128, 128, (const uint4*)(p_Bp), pre_b1, 1,
                                  p_t2, 64, NN);
    mma_gemm3<64, 1><<<MB, 256>>>(p_t2, 64, 64, (const uint4*)(p_Bp + 16384), pre_b2, 0,
                                  p_emb2, 256, NN);

    mma_gemm3<128, 0><<<MB, 256>>>(p_emb2, 256, 64, (const uint4*)(p_Bp + 24576),
                                   (const float*)nullptr, 0, p_yr, 128, NN);
    agg_kernel<<<(NN * 32 + 255) / 256, 256>>>(bl[0], 64);

    mma_gemm3<128, 0><<<MB, 256>>>(p_emb2, 256, 128, (const uint4*)(p_Bp + 40960),
                                   (const float*)nullptr, 0, p_yr, 128, NN);
    agg_kernel<<<(NN * 32 + 255) / 256, 256>>>(bl[1], 128);

    mma_gemm3<128, 0><<<MB, 256>>>(p_emb2, 256, 192, (const uint4*)(p_Bp + 73728),
                                   (const float*)nullptr, 0, p_yr, 128, NN);
    agg_kernel<<<(NN * 32 + 255) / 256, 256>>>(bl[2], 192);

    colsum_kernel<<<256, 128>>>();
    post_kernel<<<1, 256>>>(post_w1, post_b1, post_w2, post_b2, post_w3, post_b3,
                            post_w4, post_b4, out);
}

// round 10
// speedup vs baseline: 1.6143x; 1.0677x over previous
#include <cuda_runtime.h>
#include <cuda_bf16.h>
#include <math.h>
#include <stdint.h>

#define NN 50000
#define EE 800000

// ================= scratch (device globals) =================
__device__ uint32_t g_t2[(size_t)NN * 64];     // pre-mlp intermediate, split (hi,lo)
__device__ uint32_t g_emb2[(size_t)NN * 256];  // [x|h1|h2|h3] split storage
__device__ uint32_t g_yb[(size_t)NN * 64];     // per-layer [y | r] packed bf16x2 (2 cols/u32)
// packed weight images (ushort units):
//  pre1@0 (128x64), pre2@16384 (64x64), L0@24576 (64x128), L1@40960 (128x128), L2@73728 (192x128)
__device__ __align__(16) unsigned short g_Bp[122880];
__device__ int   g_cnt[NN];
__device__ int   g_rowptr[NN];
__device__ int   g_cursor[NN];
__device__ int   g_csr_src[EE];
__device__ float g_invdeg[NN];
__device__ int   g_part[256];
__device__ float g_s[256];

__device__ __forceinline__ void split2(float x, float y, uint32_t& hi, uint32_t& lo) {
    __nv_bfloat16 hx = __float2bfloat16(x), hy = __float2bfloat16(y);
    __nv_bfloat16 lx = __float2bfloat16(x - __bfloat162float(hx));
    __nv_bfloat16 ly = __float2bfloat16(y - __bfloat162float(hy));
    hi = ((uint32_t)__bfloat16_as_ushort(hy) << 16) | __bfloat16_as_ushort(hx);
    lo = ((uint32_t)__bfloat16_as_ushort(ly) << 16) | __bfloat16_as_ushort(lx);
}
__device__ __forceinline__ uint32_t packbf(float x, float y) {
    return ((uint32_t)__bfloat16_as_ushort(__float2bfloat16(y)) << 16) |
           __bfloat16_as_ushort(__float2bfloat16(x));
}

// ================= CSR build =================
__global__ void zero_kernel() {
    int i = blockIdx.x * blockDim.x + threadIdx.x;
    if (i < NN) g_cnt[i] = 0;
    if (i < 256) g_s[i] = 0.f;
}
__global__ void hist_kernel(const int* __restrict__ ei) {
    int e = blockIdx.x * blockDim.x + threadIdx.x;
    if (e < EE) atomicAdd(&g_cnt[ei[EE + e]], 1);
}
__global__ void part_kernel() {
    __shared__ int s[256];
    int t = threadIdx.x, b = blockIdx.x;
    int i = b * 256 + t;
    int v = (i < NN) ? g_cnt[i] : 0;
    s[t] = v;
    __syncthreads();
    for (int off = 128; off > 0; off >>= 1) {
        if (t < off) s[t] += s[t + off];
        __syncthreads();
    }
    if (t == 0) g_part[b] = s[0];
}
__global__ void scanp_kernel(int nb) {
    __shared__ int s[256];
    int t = threadIdx.x;
    int v = (t < nb) ? g_part[t] : 0;
    s[t] = v;
    __syncthreads();
    for (int off = 1; off < 256; off <<= 1) {
        int add = (t >= off) ? s[t - off] : 0;
        __syncthreads();
        s[t] += add;
        __syncthreads();
    }
    if (t < nb) g_part[t] = s[t] - v;  // exclusive
}
__global__ void fill_kernel() {
    __shared__ int s[256];
    int t = threadIdx.x, b = blockIdx.x;
    int i = b * 256 + t;
    int v = (i < NN) ? g_cnt[i] : 0;
    s[t] = v;
    __syncthreads();
    for (int off = 1; off < 256; off <<= 1) {
        int add = (t >= off) ? s[t - off] : 0;
        __syncthreads();
        s[t] += add;
        __syncthreads();
    }
    if (i < NN) {
        int base = g_part[b] + s[t] - v;
        g_rowptr[i] = base;
        g_cursor[i] = base;
        g_invdeg[i] = 1.0f / (float)(v > 1 ? v : 1);
    }
}
__global__ void scatter_kernel(const int* __restrict__ ei) {
    int e = blockIdx.x * blockDim.x + threadIdx.x;
    if (e < EE) {
        int dst = ei[EE + e];
        int pos = atomicAdd(&g_cursor[dst], 1);
        g_csr_src[pos] = ei[e];
    }
}

// ================= pack ALL weight images in one launch =================
__device__ __forceinline__ void pack_one(float w, int k, int n, int NTILE, int off_us) {
    int kc = k >> 4, kin = k & 15, nc = n >> 3, nin = n & 7;
    int lane = nin * 4 + ((kin & 7) >> 1);
    int reg = kin >> 3, half = kin & 1;
    int base = ((kc * (NTILE >> 3) + nc) * 32 + lane) * 4;  // u32 idx of frag
    __nv_bfloat16 hi = __float2bfloat16(w);
    __nv_bfloat16 lo = __float2bfloat16(w - __bfloat162float(hi));
    g_Bp[off_us + (base + reg) * 2 + half]     = __bfloat16_as_ushort(hi);
    g_Bp[off_us + (base + 2 + reg) * 2 + half] = __bfloat16_as_ushort(lo);
}
__global__ void packAll_kernel(const float* __restrict__ pre_w1, const float* __restrict__ pre_w2,
                               const float* __restrict__ wl0, const float* __restrict__ wr0,
                               const float* __restrict__ wl1, const float* __restrict__ wr1,
                               const float* __restrict__ wl2, const float* __restrict__ wr2,
                               const float* __restrict__ skip) {
    int idx = blockIdx.x * blockDim.x + threadIdx.x;
    if (idx < 8192) {  // pre1: K=128, N=64
        int k = idx >> 6, n = idx & 63;
        pack_one(pre_w1[k * 64 + n], k, n, 64, 0);
    } else if (idx < 12288) {  // pre2: K=64, N=64
        int j = idx - 8192;
        int k = j >> 6, n = j & 63;
        pack_one(pre_w2[k * 64 + n], k, n, 64, 16384);
    } else if (idx < 20480) {  // L0: K=64, N=128
        int j = idx - 12288;
        int k = j >> 7, n = j & 127;
        float g = 1.f / (1.f + expf(-skip[0]));
        float w = ((n < 64) ? wl0[k * 64 + n] : wr0[k * 64 + (n - 64)]) * g;
        pack_one(w, k, n, 128, 24576);
    } else if (idx < 36864) {  // L1: K=128, N=128
        int j = idx - 20480;
        int k = j >> 7, n = j & 127;
        float g = 1.f / (1.f + expf(-skip[3 + (k >> 6)]));
        float w = ((n < 64) ? wl1[k * 64 + n] : wr1[k * 64 + (n - 64)]) * g;
        pack_one(w, k, n, 128, 40960);
    } else if (idx < 61440) {  // L2: K=192, N=128
        int j = idx - 36864;
        int k = j >> 7, n = j & 127;
        float g = 1.f / (1.f + expf(-skip[6 + (k >> 6)]));
        float w = ((n < 64) ? wl2[k * 64 + n] : wr2[k * 64 + (n - 64)]) * g;
        pack_one(w, k, n, 128, 73728);
    }
}

// ================= HMMA GEMM, 2-D warp tiling ====
// INSPLIT: 1 = A is split u32 pairs; 0 = A is fp32 (split in registers)
// OUTMODE: 1 = split uint2 (hi,lo); 2 = packed bf16x2 u32 per 2 cols
__device__ __forceinline__ void mma16816(float* acc, const uint32_t* a,
                                         uint32_t b0, uint32_t b1) {
    asm volatile(
        "mma.sync.aligned.m16n8k16.row.col.f32.bf16.bf16.f32 "
        "{%0,%1,%2,%3}, {%4,%5,%6,%7}, {%8,%9}, {%0,%1,%2,%3};"
        : "+f"(acc[0]), "+f"(acc[1]), "+f"(acc[2]), "+f"(acc[3])
        : "r"(a[0]), "r"(a[1]), "r"(a[2]), "r"(a[3]), "r"(b0), "r"(b1));
}

template <int NTILE, int INSPLIT, int OUTMODE>
__global__ void __launch_bounds__(256) mma_gemm4(
    const void* __restrict__ Ain, int lda, int K,
    const uint4* __restrict__ Bp,
    const float* __restrict__ bias, int act,
    void* __restrict__ Cout, int ldc, int M) {
    constexpr int NFRAG = NTILE / 8;
    constexpr int WNF = NFRAG / 2;   // N-frags per warp
    const int tid = threadIdx.x;
    const int wid = tid >> 5, lane = tid & 31;
    const int wm = wid >> 1, wn = wid & 1;  // 4 M-warps x 2 N-warps
    const int q = lane & 3, tq = lane >> 2;
    const int rb = blockIdx.x * 128 + wm * 32 + tq;

    float acc[2][WNF][4];
#pragma unroll
    for (int m = 0; m < 2; m++)
#pragma unroll
        for (int i = 0; i < WNF; i++)
#pragma unroll
            for (int j = 0; j < 4; j++) acc[m][i][j] = 0.f;

    for (int kc = 0; kc < K / 16; kc++) {
        const int c0 = kc * 16 + 2 * q;
        uint32_t ah[2][4], al[2][4];
#pragma unroll
        for (int mf = 0; mf < 2; mf++) {
            int ra = rb + mf * 16, rc = ra + 8;
            if (INSPLIT) {
                const uint32_t* A2 = (const uint32_t*)Ain;
                uint2 p00 = make_uint2(0u, 0u), p01 = p00, p10 = p00, p11 = p00;
                if (ra < M) {
                    p00 = *(const uint2*)&A2[(size_t)ra * lda + c0];
                    p01 = *(const uint2*)&A2[(size_t)ra * lda + c0 + 8];
                }
                if (rc < M) {
                    p10 = *(const uint2*)&A2[(size_t)rc * lda + c0];
                    p11 = *(const uint2*)&A2[(size_t)rc * lda + c0 + 8];
                }
                ah[mf][0] = p00.x; ah[mf][1] = p10.x; ah[mf][2] = p01.x; ah[mf][3] = p11.x;
                al[mf][0] = p00.y; al[mf][1] = p10.y; al[mf][2] = p01.y; al[mf][3] = p11.y;
            } else {
                const float* Af = (const float*)Ain;
                float2 v00 = make_float2(0.f, 0.f), v01 = v00, v10 = v00, v11 = v00;
                if (ra < M) {
                    v00 = *(const float2*)&Af[(size_t)ra * lda + c0];
                    v01 = *(const float2*)&Af[(size_t)ra * lda + c0 + 8];
                }
                if (rc < M) {
                    v10 = *(const float2*)&Af[(size_t)rc * lda + c0];
                    v11 = *(const float2*)&Af[(size_t)rc * lda + c0 + 8];
                }
                split2(v00.x, v00.y, ah[mf][0], al[mf][0]);
                split2(v10.x, v10.y, ah[mf][1], al[mf][1]);
                split2(v01.x, v01.y, ah[mf][2], al[mf][2]);
                split2(v11.x, v11.y, ah[mf][3], al[mf][3]);
            }
        }
        const uint4* bp = Bp + (size_t)(kc * NFRAG + wn * WNF) * 32 + lane;
#pragma unroll
        for (int nc = 0; nc < WNF; nc++) {
            uint4 b = bp[nc * 32];
            mma16816(acc[0][nc], ah[0], b.x, b.y);
            mma16816(acc[0][nc], ah[0], b.z, b.w);
            mma16816(acc[0][nc], al[0], b.x, b.y);
            mma16816(acc[1][nc], ah[1], b.x, b.y);
            mma16816(acc[1][nc], ah[1], b.z, b.w);
            mma16816(acc[1][nc], al[1], b.x, b.y);
        }
    }

#pragma unroll
    for (int nc = 0; nc < WNF; nc++) {
        int col = wn * (NTILE / 2) + nc * 8 + 2 * q;
        float b0v = bias ? bias[col] : 0.f;
        float b1v = bias ? bias[col + 1] : 0.f;
#pragma unroll
        for (int mf = 0; mf < 2; mf++) {
            int ra = rb + mf * 16, rc = ra + 8;
            float x0 = acc[mf][nc][0] + b0v, y0 = acc[mf][nc][1] + b1v;
            float x1 = acc[mf][nc][2] + b0v, y1 = acc[mf][nc][3] + b1v;
            if (act) {
                x0 = fmaxf(x0, 0.f); y0 = fmaxf(y0, 0.f);
                x1 = fmaxf(x1, 0.f); y1 = fmaxf(y1, 0.f);
            }
            if (OUTMODE == 1) {
                uint32_t* Cu = (uint32_t*)Cout;
                uint32_t hi, lo;
                if (ra < M) {
                    split2(x0, y0, hi, lo);
                    *(uint2*)&Cu[(size_t)ra * ldc + col] = make_uint2(hi, lo);
                }
                if (rc < M) {
                    split2(x1, y1, hi, lo);
                    *(uint2*)&Cu[(size_t)rc * ldc + col] = make_uint2(hi, lo);
                }
            } else {
                uint32_t* Cu = (uint32_t*)Cout;
                if (ra < M) Cu[(size_t)ra * ldc + (col >> 1)] = packbf(x0, y0);
                if (rc < M) Cu[(size_t)rc * ldc + (col >> 1)] = packbf(x1, y1);
            }
        }
    }
}

// ================= aggregation: one warp per node, bf16 y gathers ==========
__global__ void agg_kernel(const float* __restrict__ bl, int outcol) {
    int gw = (blockIdx.x * blockDim.x + threadIdx.x) >> 5;
    int lane = threadIdx.x & 31;
    if (gw >= NN) return;
    const int n = gw;
    const int beg = g_rowptr[n], cnt = g_cnt[n];
    const uint32_t* __restrict__ yb = g_yb;
    float sx = 0.f, sy = 0.f;
    for (int k = 0; k < cnt; k++) {
        int src = g_csr_src[beg + k];
        uint32_t v = yb[(size_t)src * 64 + lane];
        sx += __uint_as_float(v << 16);
        sy += __uint_as_float(v & 0xFFFF0000u);
    }
    float inv = g_invdeg[n];
    uint32_t rv = yb[(size_t)n * 64 + 32 + lane];
    float r0 = __uint_as_float(rv << 16);
    float r1 = __uint_as_float(rv & 0xFFFF0000u);
    float h0 = fmaxf(sx * inv + bl[2 * lane] + r0, 0.f);
    float h1 = fmaxf(sy * inv + bl[2 * lane + 1] + r1, 0.f);
    uint32_t hi, lo;
    split2(h0, h1, hi, lo);
    *(uint2*)&g_emb2[(size_t)n * 256 + outcol + 2 * lane] = make_uint2(hi, lo);
}

// ================= column sum over split emb + post mlp =================
__global__ void colsum_kernel() {
    int t = threadIdx.x;  // 128 threads: col pair (2t, 2t+1)
    int per = (NN + gridDim.x - 1) / gridDim.x;
    int n0 = blockIdx.x * per;
    int n1 = n0 + per;
    if (n1 > NN) n1 = NN;
    float s0 = 0.f, s1 = 0.f;
    for (int n = n0; n < n1; n++) {
        uint2 w = *(const uint2*)&g_emb2[(size_t)n * 256 + 2 * t];
        s0 += __uint_as_float(w.x << 16) + __uint_as_float(w.y << 16);
        s1 += __uint_as_float(w.x & 0xFFFF0000u) + __uint_as_float(w.y & 0xFFFF0000u);
    }
    atomicAdd(&g_s[2 * t], s0);
    atomicAdd(&g_s[2 * t + 1], s1);
}
__global__ void post_kernel(const float* __restrict__ w1, const float* __restrict__ b1,
                            const float* __restrict__ w2, const float* __restrict__ b2,
                            const float* __restrict__ w3, const float* __restrict__ b3,
                            const float* __restrict__ w4, const float* __restrict__ b4,
                            float* __restrict__ out) {
    __shared__ float s1[64], s2[64], s3[256];
    int t = threadIdx.x;
    if (t < 64) {
        float a = b1[t];
        for (int k = 0; k < 256; k++) a += g_s[k] * w1[k * 64 + t];
        s1[t] = (a > 0.f) ? a : 0.1f * a;
    }
    __syncthreads();
    if (t < 64) {
        float a = b2[t];
        for (int k = 0; k < 64; k++) a += s1[k] * w2[k * 64 + t];
        s2[t] = fmaxf(a, 0.f);
    }
    __syncthreads();
    {
        float a = b3[t];
        for (int k = 0; k < 64; k++) a += s2[k] * w3[k * 256 + t];
        s3[t] = fmaxf(a, 0.f);
    }
    __syncthreads();
    if (t < 64) {
        float a = b4[t];
        for (int k = 0; k < 256; k++) a += s3[k] * w4[k * 64 + t];
        out[t] = a;
    }
}

// ================= launch =================
extern "C" void kernel_launch(void* const* d_in, const int* in_sizes, int n_in,
                              void* d_out, int out_size) {
    const float* node_features = (const float*)d_in[0];
    const int*   edge_index    = (const int*)d_in[1];
    const float* pre_w1 = (const float*)d_in[2];
    const float* pre_b1 = (const float*)d_in[3];
    const float* pre_w2 = (const float*)d_in[4];
    const float* pre_b2 = (const float*)d_in[5];
    const float* skip   = (const float*)d_in[6];
    const float* wl[3] = {(const float*)d_in[7], (const float*)d_in[10], (const float*)d_in[13]};
    const float* bl[3] = {(const float*)d_in[8], (const float*)d_in[11], (const float*)d_in[14]};
    const float* wr[3] = {(const float*)d_in[9], (const float*)d_in[12], (const float*)d_in[15]};
    const float* post_w1 = (const float*)d_in[16];
    const float* post_b1 = (const float*)d_in[17];
    const float* post_w2 = (const float*)d_in[18];
    const float* post_b2 = (const float*)d_in[19];
    const float* post_w3 = (const float*)d_in[20];
    const float* post_b3 = (const float*)d_in[21];
    const float* post_w4 = (const float*)d_in[22];
    const float* post_b4 = (const float*)d_in[23];
    float* out = (float*)d_out;

    uint32_t *p_t2, *p_emb2, *p_yb;
    unsigned short* p_Bp;
    cudaGetSymbolAddress((void**)&p_t2, g_t2);
    cudaGetSymbolAddress((void**)&p_emb2, g_emb2);
    cudaGetSymbolAddress((void**)&p_yb, g_yb);
    cudaGetSymbolAddress((void**)&p_Bp, g_Bp);

    const int NB = (NN + 255) / 256;  // 196
    const int MB = (NN + 127) / 128;  // 391

    // CSR build
    zero_kernel<<<NB, 256>>>();
    hist_kernel<<<(EE + 255) / 256, 256>>>(edge_index);
    part_kernel<<<NB, 256>>>();
    scanp_kernel<<<1, 256>>>(NB);
    fill_kernel<<<NB, 256>>>();
    scatter_kernel<<<(EE + 255) / 256, 256>>>(edge_index);

    // pack weights
    packAll_kernel<<<(61440 + 255) / 256, 256>>>(pre_w1, pre_w2, wl[0], wr[0], wl[1], wr[1],
                                                 wl[2], wr[2], skip);
    // pre-mlp GEMM 1: reads fp32 X directly, splits in regs
    mma_gemm4<64, 0, 1><<<MB, 256>>>(node_features, 128, 128, (const uint4*)(p_Bp),
                                     pre_b1, 1, p_t2, 64, NN);
    // pre-mlp GEMM 2
    mma_gemm4<64, 1, 1><<<MB, 256>>>(p_t2, 64, 64, (const uint4*)(p_Bp + 16384),
                                     pre_b2, 0, p_emb2, 256, NN);

    mma_gemm4<128, 1, 2><<<MB, 256>>>(p_emb2, 256, 64, (const uint4*)(p_Bp + 24576),
                                      (const float*)nullptr, 0, p_yb, 64, NN);
    agg_kernel<<<(NN * 32 + 255) / 256, 256>>>(bl[0], 64);

    mma_gemm4<128, 1, 2><<<MB, 256>>>(p_emb2, 256, 128, (const uint4*)(p_Bp + 40960),
                                      (const float*)nullptr, 0, p_yb, 64, NN);
    agg_kernel<<<(NN * 32 + 255) / 256, 256>>>(bl[1], 128);

    mma_gemm4<128, 1, 2><<<MB, 256>>>(p_emb2, 256, 192, (const uint4*)(p_Bp + 73728),
                                      (const float*)nullptr, 0, p_yb, 64, NN);
    agg_kernel<<<(NN * 32 + 255) / 256, 256>>>(bl[2], 192);

    colsum_kernel<<<256, 128>>>();
    post_kernel<<<1, 256>>>(post_w1, post_b1, post_w2, post_b2, post_w3, post_b3,
                            post_w4, post_b4, out);
}

// round 11
// speedup vs baseline: 1.6763x; 1.0384x over previous
#include <cuda_runtime.h>
#include <cuda_bf16.h>
#include <math.h>
#include <stdint.h>

#define NN 50000
#define EE 800000

// ================= scratch (device globals) =================
__device__ uint32_t g_emb2[(size_t)NN * 256];  // [x|h1|h2|h3] split storage
__device__ uint32_t g_yb[(size_t)NN * 64];     // per-layer [y | r] packed bf16x2
// packed weight images (ushort units):
//  pre1@0 (128x64), pre2@16384 (64x64), L0@24576 (64x128), L1@40960 (128x128), L2@73728 (192x128)
__device__ __align__(16) unsigned short g_Bp[122880];
__device__ int   g_cnt[NN];
__device__ int   g_rowptr[NN];
__device__ int   g_cursor[NN];
__device__ int   g_csr_src[EE];
__device__ float g_invdeg[NN];
__device__ int   g_part[256];
__device__ float g_s[256];

__device__ __forceinline__ void split2(float x, float y, uint32_t& hi, uint32_t& lo) {
    __nv_bfloat16 hx = __float2bfloat16(x), hy = __float2bfloat16(y);
    __nv_bfloat16 lx = __float2bfloat16(x - __bfloat162float(hx));
    __nv_bfloat16 ly = __float2bfloat16(y - __bfloat162float(hy));
    hi = ((uint32_t)__bfloat16_as_ushort(hy) << 16) | __bfloat16_as_ushort(hx);
    lo = ((uint32_t)__bfloat16_as_ushort(ly) << 16) | __bfloat16_as_ushort(lx);
}
__device__ __forceinline__ uint32_t packbf(float x, float y) {
    return ((uint32_t)__bfloat16_as_ushort(__float2bfloat16(y)) << 16) |
           __bfloat16_as_ushort(__float2bfloat16(x));
}

// ================= CSR build =================
__global__ void zero_kernel() {
    int i = blockIdx.x * blockDim.x + threadIdx.x;
    if (i < NN) g_cnt[i] = 0;
    if (i < 256) g_s[i] = 0.f;
}
__global__ void hist2_kernel(const int* __restrict__ ei) {
    int e = (blockIdx.x * blockDim.x + threadIdx.x) * 2;
    if (e < EE) {
        int2 d = *(const int2*)&ei[EE + e];
        atomicAdd(&g_cnt[d.x], 1);
        atomicAdd(&g_cnt[d.y], 1);
    }
}
__global__ void part_kernel() {
    __shared__ int s[256];
    int t = threadIdx.x, b = blockIdx.x;
    int i = b * 256 + t;
    int v = (i < NN) ? g_cnt[i] : 0;
    s[t] = v;
    __syncthreads();
    for (int off = 128; off > 0; off >>= 1) {
        if (t < off) s[t] += s[t + off];
        __syncthreads();
    }
    if (t == 0) g_part[b] = s[0];
}
// fill: per-block scan of all partials (redundant but removes serial launch)
__global__ void fill2_kernel(int nb) {
    __shared__ int sp[256];
    __shared__ int sl[256];
    int t = threadIdx.x, b = blockIdx.x;
    sp[t] = (t < nb) ? g_part[t] : 0;
    __syncthreads();
    for (int off = 1; off < 256; off <<= 1) {
        int a = (t >= off) ? sp[t - off] : 0;
        __syncthreads();
        sp[t] += a;
        __syncthreads();
    }
    int blockbase = (b == 0) ? 0 : sp[b - 1];
    int i = b * 256 + t;
    int v = (i < NN) ? g_cnt[i] : 0;
    sl[t] = v;
    __syncthreads();
    for (int off = 1; off < 256; off <<= 1) {
        int a = (t >= off) ? sl[t - off] : 0;
        __syncthreads();
        sl[t] += a;
        __syncthreads();
    }
    if (i < NN) {
        int base = blockbase + sl[t] - v;
        g_rowptr[i] = base;
        g_cursor[i] = base;
        g_invdeg[i] = 1.0f / (float)(v > 1 ? v : 1);
    }
}
__global__ void scatter2_kernel(const int* __restrict__ ei) {
    int e = (blockIdx.x * blockDim.x + threadIdx.x) * 2;
    if (e < EE) {
        int2 s = *(const int2*)&ei[e];
        int2 d = *(const int2*)&ei[EE + e];
        int p0 = atomicAdd(&g_cursor[d.x], 1);
        g_csr_src[p0] = s.x;
        int p1 = atomicAdd(&g_cursor[d.y], 1);
        g_csr_src[p1] = s.y;
    }
}

// ================= pack ALL weight images in one launch =================
__device__ __forceinline__ void pack_one(float w, int k, int n, int NTILE, int off_us) {
    int kc = k >> 4, kin = k & 15, nc = n >> 3, nin = n & 7;
    int lane = nin * 4 + ((kin & 7) >> 1);
    int reg = kin >> 3, half = kin & 1;
    int base = ((kc * (NTILE >> 3) + nc) * 32 + lane) * 4;
    __nv_bfloat16 hi = __float2bfloat16(w);
    __nv_bfloat16 lo = __float2bfloat16(w - __bfloat162float(hi));
    g_Bp[off_us + (base + reg) * 2 + half]     = __bfloat16_as_ushort(hi);
    g_Bp[off_us + (base + 2 + reg) * 2 + half] = __bfloat16_as_ushort(lo);
}
__global__ void packAll_kernel(const float* __restrict__ pre_w1, const float* __restrict__ pre_w2,
                               const float* __restrict__ wl0, const float* __restrict__ wr0,
                               const float* __restrict__ wl1, const float* __restrict__ wr1,
                               const float* __restrict__ wl2, const float* __restrict__ wr2,
                               const float* __restrict__ skip) {
    int idx = blockIdx.x * blockDim.x + threadIdx.x;
    if (idx < 8192) {
        int k = idx >> 6, n = idx & 63;
        pack_one(pre_w1[k * 64 + n], k, n, 64, 0);
    } else if (idx < 12288) {
        int j = idx - 8192;
        int k = j >> 6, n = j & 63;
        pack_one(pre_w2[k * 64 + n], k, n, 64, 16384);
    } else if (idx < 20480) {
        int j = idx - 12288;
        int k = j >> 7, n = j & 127;
        float g = 1.f / (1.f + expf(-skip[0]));
        float w = ((n < 64) ? wl0[k * 64 + n] : wr0[k * 64 + (n - 64)]) * g;
        pack_one(w, k, n, 128, 24576);
    } else if (idx < 36864) {
        int j = idx - 20480;
        int k = j >> 7, n = j & 127;
        float g = 1.f / (1.f + expf(-skip[3 + (k >> 6)]));
        float w = ((n < 64) ? wl1[k * 64 + n] : wr1[k * 64 + (n - 64)]) * g;
        pack_one(w, k, n, 128, 40960);
    } else if (idx < 61440) {
        int j = idx - 36864;
        int k = j >> 7, n = j & 127;
        float g = 1.f / (1.f + expf(-skip[6 + (k >> 6)]));
        float w = ((n < 64) ? wl2[k * 64 + n] : wr2[k * 64 + (n - 64)]) * g;
        pack_one(w, k, n, 128, 73728);
    }
}

// ================= HMMA helpers =================
__device__ __forceinline__ void mma16816(float* acc, const uint32_t* a,
                                         uint32_t b0, uint32_t b1) {
    asm volatile(
        "mma.sync.aligned.m16n8k16.row.col.f32.bf16.bf16.f32 "
        "{%0,%1,%2,%3}, {%4,%5,%6,%7}, {%8,%9}, {%0,%1,%2,%3};"
        : "+f"(acc[0]), "+f"(acc[1]), "+f"(acc[2]), "+f"(acc[3])
        : "r"(a[0]), "r"(a[1]), "r"(a[2]), "r"(a[3]), "r"(b0), "r"(b1));
}

#define SMS 66  // smem row stride (u32) - avoids bank conflicts

// ================= fused pre-MLP + L0 GEMM =================
// Phase1: t = relu(X@W1+b1)  K=128,N=64   -> smem
// Phase2: x = t@W2+b2        K=64, N=64   -> smem + emb2
// Phase3: y0|r0 = x@W0g      K=64, N=128  -> yb (packed bf16)
__global__ void __launch_bounds__(256) fused_pre_kernel(
    const float* __restrict__ X,
    const uint4* __restrict__ B1, const float* __restrict__ b1v,
    const uint4* __restrict__ B2, const float* __restrict__ b2v,
    const uint4* __restrict__ B0,
    uint32_t* __restrict__ emb2, uint32_t* __restrict__ yb, int M) {
    extern __shared__ uint32_t sh[];
    uint32_t* t_s = sh;                 // [128][SMS]
    uint32_t* x_s = sh + 128 * SMS;     // [128][SMS]
    const int tid = threadIdx.x;
    const int wid = tid >> 5, lane = tid & 31;
    const int wm = wid >> 1, wn = wid & 1;
    const int q = lane & 3, tq = lane >> 2;
    const int lr0 = wm * 32 + tq;       // local row base
    const int gb = blockIdx.x * 128;

    // ---------- phase 1 ----------
    {
        float acc[2][4][4];
#pragma unroll
        for (int m = 0; m < 2; m++)
#pragma unroll
            for (int i = 0; i < 4; i++)
#pragma unroll
                for (int j = 0; j < 4; j++) acc[m][i][j] = 0.f;
        for (int kc = 0; kc < 8; kc++) {
            const int c0 = kc * 16 + 2 * q;
            uint32_t ah[2][4], al[2][4];
#pragma unroll
            for (int mf = 0; mf < 2; mf++) {
                int ra = gb + lr0 + mf * 16, rc = ra + 8;
                float2 v00 = make_float2(0.f, 0.f), v01 = v00, v10 = v00, v11 = v00;
                if (ra < M) {
                    v00 = *(const float2*)&X[(size_t)ra * 128 + c0];
                    v01 = *(const float2*)&X[(size_t)ra * 128 + c0 + 8];
                }
                if (rc < M) {
                    v10 = *(const float2*)&X[(size_t)rc * 128 + c0];
                    v11 = *(const float2*)&X[(size_t)rc * 128 + c0 + 8];
                }
                split2(v00.x, v00.y, ah[mf][0], al[mf][0]);
                split2(v10.x, v10.y, ah[mf][1], al[mf][1]);
                split2(v01.x, v01.y, ah[mf][2], al[mf][2]);
                split2(v11.x, v11.y, ah[mf][3], al[mf][3]);
            }
            const uint4* bp = B1 + (size_t)(kc * 8 + wn * 4) * 32 + lane;
#pragma unroll
            for (int nc = 0; nc < 4; nc++) {
                uint4 b = bp[nc * 32];
                mma16816(acc[0][nc], ah[0], b.x, b.y);
                mma16816(acc[0][nc], ah[0], b.z, b.w);
                mma16816(acc[0][nc], al[0], b.x, b.y);
                mma16816(acc[1][nc], ah[1], b.x, b.y);
                mma16816(acc[1][nc], ah[1], b.z, b.w);
                mma16816(acc[1][nc], al[1], b.x, b.y);
            }
        }
#pragma unroll
        for (int nc = 0; nc < 4; nc++) {
            int col = wn * 32 + nc * 8 + 2 * q;
            float bb0 = b1v[col], bb1 = b1v[col + 1];
#pragma unroll
            for (int mf = 0; mf < 2; mf++) {
                int la = lr0 + mf * 16, lc = la + 8;
                float x0 = fmaxf(acc[mf][nc][0] + bb0, 0.f);
                float y0 = fmaxf(acc[mf][nc][1] + bb1, 0.f);
                float x1 = fmaxf(acc[mf][nc][2] + bb0, 0.f);
                float y1 = fmaxf(acc[mf][nc][3] + bb1, 0.f);
                uint32_t hi, lo;
                split2(x0, y0, hi, lo);
                t_s[la * SMS + col] = hi;
                t_s[la * SMS + col + 1] = lo;
                split2(x1, y1, hi, lo);
                t_s[lc * SMS + col] = hi;
                t_s[lc * SMS + col + 1] = lo;
            }
        }
    }
    __syncthreads();

    // ---------- phase 2 ----------
    {
        float acc[2][4][4];
#pragma unroll
        for (int m = 0; m < 2; m++)
#pragma unroll
            for (int i = 0; i < 4; i++)
#pragma unroll
                for (int j = 0; j < 4; j++) acc[m][i][j] = 0.f;
        for (int kc = 0; kc < 4; kc++) {
            const int c0 = kc * 16 + 2 * q;
            uint32_t ah[2][4], al[2][4];
#pragma unroll
            for (int mf = 0; mf < 2; mf++) {
                int la = lr0 + mf * 16, lc = la + 8;
                uint2 p00 = *(const uint2*)&t_s[la * SMS + c0];
                uint2 p01 = *(const uint2*)&t_s[la * SMS + c0 + 8];
                uint2 p10 = *(const uint2*)&t_s[lc * SMS + c0];
                uint2 p11 = *(const uint2*)&t_s[lc * SMS + c0 + 8];
                ah[mf][0] = p00.x; ah[mf][1] = p10.x; ah[mf][2] = p01.x; ah[mf][3] = p11.x;
                al[mf][0] = p00.y; al[mf][1] = p10.y; al[mf][2] = p01.y; al[mf][3] = p11.y;
            }
            const uint4* bp = B2 + (size_t)(kc * 8 + wn * 4) * 32 + lane;
#pragma unroll
            for (int nc = 0; nc < 4; nc++) {
                uint4 b = bp[nc * 32];
                mma16816(acc[0][nc], ah[0], b.x, b.y);
                mma16816(acc[0][nc], ah[0], b.z, b.w);
                mma16816(acc[0][nc], al[0], b.x, b.y);
                mma16816(acc[1][nc], ah[1], b.x, b.y);
                mma16816(acc[1][nc], ah[1], b.z, b.w);
                mma16816(acc[1][nc], al[1], b.x, b.y);
            }
        }
        __syncthreads();  // t_s reads done before x_s writes alias? (separate arrays; sync for phase order clarity)
#pragma unroll
        for (int nc = 0; nc < 4; nc++) {
            int col = wn * 32 + nc * 8 + 2 * q;
            float bb0 = b2v[col], bb1 = b2v[col + 1];
#pragma unroll
            for (int mf = 0; mf < 2; mf++) {
                int la = lr0 + mf * 16, lc = la + 8;
                float x0 = acc[mf][nc][0] + bb0, y0 = acc[mf][nc][1] + bb1;
                float x1 = acc[mf][nc][2] + bb0, y1 = acc[mf][nc][3] + bb1;
                uint32_t hi, lo;
                split2(x0, y0, hi, lo);
                x_s[la * SMS + col] = hi;
                x_s[la * SMS + col + 1] = lo;
                if (gb + la < M)
                    *(uint2*)&emb2[(size_t)(gb + la) * 256 + col] = make_uint2(hi, lo);
                split2(x1, y1, hi, lo);
                x_s[lc * SMS + col] = hi;
                x_s[lc * SMS + col + 1] = lo;
                if (gb + lc < M)
                    *(uint2*)&emb2[(size_t)(gb + lc) * 256 + col] = make_uint2(hi, lo);
            }
        }
    }
    __syncthreads();

    // ---------- phase 3: K=64, NTILE=128 ----------
    {
        float acc[2][8][4];
#pragma unroll
        for (int m = 0; m < 2; m++)
#pragma unroll
            for (int i = 0; i < 8; i++)
#pragma unroll
                for (int j = 0; j < 4; j++) acc[m][i][j] = 0.f;
        for (int kc = 0; kc < 4; kc++) {
            const int c0 = kc * 16 + 2 * q;
            uint32_t ah[2][4], al[2][4];
#pragma unroll
            for (int mf = 0; mf < 2; mf++) {
                int la = lr0 + mf * 16, lc = la + 8;
                uint2 p00 = *(const uint2*)&x_s[la * SMS + c0];
                uint2 p01 = *(const uint2*)&x_s[la * SMS + c0 + 8];
                uint2 p10 = *(const uint2*)&x_s[lc * SMS + c0];
                uint2 p11 = *(const uint2*)&x_s[lc * SMS + c0 + 8];
                ah[mf][0] = p00.x; ah[mf][1] = p10.x; ah[mf][2] = p01.x; ah[mf][3] = p11.x;
                al[mf][0] = p00.y; al[mf][1] = p10.y; al[mf][2] = p01.y; al[mf][3] = p11.y;
            }
            const uint4* bp = B0 + (size_t)(kc * 16 + wn * 8) * 32 + lane;
#pragma unroll
            for (int nc = 0; nc < 8; nc++) {
                uint4 b = bp[nc * 32];
                mma16816(acc[0][nc], ah[0], b.x, b.y);
                mma16816(acc[0][nc], ah[0], b.z, b.w);
                mma16816(acc[0][nc], al[0], b.x, b.y);
                mma16816(acc[1][nc], ah[1], b.x, b.y);
                mma16816(acc[1][nc], ah[1], b.z, b.w);
                mma16816(acc[1][nc], al[1], b.x, b.y);
            }
        }
#pragma unroll
        for (int nc = 0; nc < 8; nc++) {
            int col = wn * 64 + nc * 8 + 2 * q;
#pragma unroll
            for (int mf = 0; mf < 2; mf++) {
                int ra = gb + lr0 + mf * 16, rc = ra + 8;
                if (ra < M) yb[(size_t)ra * 64 + (col >> 1)] =
                    packbf(acc[mf][nc][0], acc[mf][nc][1]);
                if (rc < M) yb[(size_t)rc * 64 + (col >> 1)] =
                    packbf(acc[mf][nc][2], acc[mf][nc][3]);
            }
        }
    }
}

// ================= standalone GEMM (layers 1,2): split A -> packed bf16 out ====
template <int NTILE>
__global__ void __launch_bounds__(256) mma_gemm4(
    const uint32_t* __restrict__ A2, int lda, int K,
    const uint4* __restrict__ Bp,
    uint32_t* __restrict__ Cout, int ldc, int M) {
    constexpr int NFRAG = NTILE / 8;
    constexpr int WNF = NFRAG / 2;
    const int tid = threadIdx.x;
    const int wid = tid >> 5, lane = tid & 31;
    const int wm = wid >> 1, wn = wid & 1;
    const int q = lane & 3, tq = lane >> 2;
    const int rb = blockIdx.x * 128 + wm * 32 + tq;

    float acc[2][WNF][4];
#pragma unroll
    for (int m = 0; m < 2; m++)
#pragma unroll
        for (int i = 0; i < WNF; i++)
#pragma unroll
            for (int j = 0; j < 4; j++) acc[m][i][j] = 0.f;

    for (int kc = 0; kc < K / 16; kc++) {
        const int c0 = kc * 16 + 2 * q;
        uint32_t ah[2][4], al[2][4];
#pragma unroll
        for (int mf = 0; mf < 2; mf++) {
            int ra = rb + mf * 16, rc = ra + 8;
            uint2 p00 = make_uint2(0u, 0u), p01 = p00, p10 = p00, p11 = p00;
            if (ra < M) {
                p00 = *(const uint2*)&A2[(size_t)ra * lda + c0];
                p01 = *(const uint2*)&A2[(size_t)ra * lda + c0 + 8];
            }
            if (rc < M) {
                p10 = *(const uint2*)&A2[(size_t)rc * lda + c0];
                p11 = *(const uint2*)&A2[(size_t)rc * lda + c0 + 8];
            }
            ah[mf][0] = p00.x; ah[mf][1] = p10.x; ah[mf][2] = p01.x; ah[mf][3] = p11.x;
            al[mf][0] = p00.y; al[mf][1] = p10.y; al[mf][2] = p01.y; al[mf][3] = p11.y;
        }
        const uint4* bp = Bp + (size_t)(kc * NFRAG + wn * WNF) * 32 + lane;
#pragma unroll
        for (int nc = 0; nc < WNF; nc++) {
            uint4 b = bp[nc * 32];
            mma16816(acc[0][nc], ah[0], b.x, b.y);
            mma16816(acc[0][nc], ah[0], b.z, b.w);
            mma16816(acc[0][nc], al[0], b.x, b.y);
            mma16816(acc[1][nc], ah[1], b.x, b.y);
            mma16816(acc[1][nc], ah[1], b.z, b.w);
            mma16816(acc[1][nc], al[1], b.x, b.y);
        }
    }

#pragma unroll
    for (int nc = 0; nc < WNF; nc++) {
        int col = wn * (NTILE / 2) + nc * 8 + 2 * q;
#pragma unroll
        for (int mf = 0; mf < 2; mf++) {
            int ra = rb + mf * 16, rc = ra + 8;
            if (ra < M) Cout[(size_t)ra * ldc + (col >> 1)] =
                packbf(acc[mf][nc][0], acc[mf][nc][1]);
            if (rc < M) Cout[(size_t)rc * ldc + (col >> 1)] =
                packbf(acc[mf][nc][2], acc[mf][nc][3]);
        }
    }
}

// ================= aggregation: one warp per node, bf16 y gathers ==========
__global__ void agg_kernel(const float* __restrict__ bl, int outcol) {
    int gw = (blockIdx.x * blockDim.x + threadIdx.x) >> 5;
    int lane = threadIdx.x & 31;
    if (gw >= NN) return;
    const int n = gw;
    const int beg = g_rowptr[n], cnt = g_cnt[n];
    const uint32_t* __restrict__ yb = g_yb;
    float sx = 0.f, sy = 0.f;
    for (int k = 0; k < cnt; k++) {
        int src = g_csr_src[beg + k];
        uint32_t v = yb[(size_t)src * 64 + lane];
        sx += __uint_as_float(v << 16);
        sy += __uint_as_float(v & 0xFFFF0000u);
    }
    float inv = g_invdeg[n];
    uint32_t rv = yb[(size_t)n * 64 + 32 + lane];
    float r0 = __uint_as_float(rv << 16);
    float r1 = __uint_as_float(rv & 0xFFFF0000u);
    float h0 = fmaxf(sx * inv + bl[2 * lane] + r0, 0.f);
    float h1 = fmaxf(sy * inv + bl[2 * lane + 1] + r1, 0.f);
    uint32_t hi, lo;
    split2(h0, h1, hi, lo);
    *(uint2*)&g_emb2[(size_t)n * 256 + outcol + 2 * lane] = make_uint2(hi, lo);
}

// ================= column sum over split emb + post mlp =================
__global__ void colsum_kernel() {
    int t = threadIdx.x;  // 128 threads: col pair (2t, 2t+1)
    int per = (NN + gridDim.x - 1) / gridDim.x;
    int n0 = blockIdx.x * per;
    int n1 = n0 + per;
    if (n1 > NN) n1 = NN;
    float s0 = 0.f, s1 = 0.f;
    for (int n = n0; n < n1; n++) {
        uint2 w = *(const uint2*)&g_emb2[(size_t)n * 256 + 2 * t];
        s0 += __uint_as_float(w.x << 16) + __uint_as_float(w.y << 16);
        s1 += __uint_as_float(w.x & 0xFFFF0000u) + __uint_as_float(w.y & 0xFFFF0000u);
    }
    atomicAdd(&g_s[2 * t], s0);
    atomicAdd(&g_s[2 * t + 1], s1);
}
__global__ void post_kernel(const float* __restrict__ w1, const float* __restrict__ b1,
                            const float* __restrict__ w2, const float* __restrict__ b2,
                            const float* __restrict__ w3, const float* __restrict__ b3,
                            const float* __restrict__ w4, const float* __restrict__ b4,
                            float* __restrict__ out) {
    __shared__ float s1[64], s2[64], s3[256];
    int t = threadIdx.x;
    if (t < 64) {
        float a = b1[t];
        for (int k = 0; k < 256; k++) a += g_s[k] * w1[k * 64 + t];
        s1[t] = (a > 0.f) ? a : 0.1f * a;
    }
    __syncthreads();
    if (t < 64) {
        float a = b2[t];
        for (int k = 0; k < 64; k++) a += s1[k] * w2[k * 64 + t];
        s2[t] = fmaxf(a, 0.f);
    }
    __syncthreads();
    {
        float a = b3[t];
        for (int k = 0; k < 64; k++) a += s2[k] * w3[k * 256 + t];
        s3[t] = fmaxf(a, 0.f);
    }
    __syncthreads();
    if (t < 64) {
        float a = b4[t];
        for (int k = 0; k < 256; k++) a += s3[k] * w4[k * 64 + t];
        out[t] = a;
    }
}

// ================= launch =================
extern "C" void kernel_launch(void* const* d_in, const int* in_sizes, int n_in,
                              void* d_out, int out_size) {
    const float* node_features = (const float*)d_in[0];
    const int*   edge_index    = (const int*)d_in[1];
    const float* pre_w1 = (const float*)d_in[2];
    const float* pre_b1 = (const float*)d_in[3];
    const float* pre_w2 = (const float*)d_in[4];
    const float* pre_b2 = (const float*)d_in[5];
    const float* skip   = (const float*)d_in[6];
    const float* wl[3] = {(const float*)d_in[7], (const float*)d_in[10], (const float*)d_in[13]};
    const float* bl[3] = {(const float*)d_in[8], (const float*)d_in[11], (const float*)d_in[14]};
    const float* wr[3] = {(const float*)d_in[9], (const float*)d_in[12], (const float*)d_in[15]};
    const float* post_w1 = (const float*)d_in[16];
    const float* post_b1 = (const float*)d_in[17];
    const float* post_w2 = (const float*)d_in[18];
    const float* post_b2 = (const float*)d_in[19];
    const float* post_w3 = (const float*)d_in[20];
    const float* post_b3 = (const float*)d_in[21];
    const float* post_w4 = (const float*)d_in[22];
    const float* post_b4 = (const float*)d_in[23];
    float* out = (float*)d_out;

    uint32_t *p_emb2, *p_yb;
    unsigned short* p_Bp;
    cudaGetSymbolAddress((void**)&p_emb2, g_emb2);
    cudaGetSymbolAddress((void**)&p_yb, g_yb);
    cudaGetSymbolAddress((void**)&p_Bp, g_Bp);

    const int NB = (NN + 255) / 256;  // 196
    const int MB = (NN + 127) / 128;  // 391
    const int SMEM_FUSED = 2 * 128 * SMS * 4;  // 67584 bytes

    static int smem_set = 0;
    cudaFuncSetAttribute(fused_pre_kernel, cudaFuncAttributeMaxDynamicSharedMemorySize,
                         SMEM_FUSED);
    (void)smem_set;

    // CSR build
    zero_kernel<<<NB, 256>>>();
    hist2_kernel<<<(EE / 2 + 255) / 256, 256>>>(edge_index);
    part_kernel<<<NB, 256>>>();
    fill2_kernel<<<NB, 256>>>(NB);
    scatter2_kernel<<<(EE / 2 + 255) / 256, 256>>>(edge_index);

    // pack weights, fused pre-MLP + L0
    packAll_kernel<<<(61440 + 255) / 256, 256>>>(pre_w1, pre_w2, wl[0], wr[0], wl[1], wr[1],
                                                 wl[2], wr[2], skip);
    fused_pre_kernel<<<MB, 256, SMEM_FUSED>>>(
        node_features, (const uint4*)(p_Bp), pre_b1,
        (const uint4*)(p_Bp + 16384), pre_b2,
        (const uint4*)(p_Bp + 24576), p_emb2, p_yb, NN);

    agg_kernel<<<(NN * 32 + 255) / 256, 256>>>(bl[0], 64);

    mma_gemm4<128><<<MB, 256>>>(p_emb2, 256, 128, (const uint4*)(p_Bp + 40960),
                                p_yb, 64, NN);
    agg_kernel<<<(NN * 32 + 255) / 256, 256>>>(bl[1], 128);

    mma_gemm4<128><<<MB, 256>>>(p_emb2, 256, 192, (const uint4*)(p_Bp + 73728),
                                p_yb, 64, NN);
    agg_kernel<<<(NN * 32 + 255) / 256, 256>>>(bl[2], 192);

    colsum_kernel<<<256, 128>>>();
    post_kernel<<<1, 256>>>(post_w1, post_b1, post_w2, post_b2, post_w3, post_b3,
                            post_w4, post_b4, out);
}

// round 13
// speedup vs baseline: 2.0743x; 1.2374x over previous
#include <cuda_runtime.h>
#include <cuda_bf16.h>
#include <math.h>
#include <stdint.h>

#define NN 50000
#define EE 800000

// ================= scratch (device globals) =================
__device__ uint32_t g_embp[(size_t)NN * 128];  // [x|h1|h2|h3] packed bf16x2 (2 cols/u32)
__device__ uint32_t g_yb[(size_t)NN * 64];     // per-layer [y | r] packed bf16x2
// packed hi/lo weight images, uint4 frags [bh0,bh1,bl0,bl1] (ushort units):
//  pre1@0 (128x64), pre2@16384 (64x64), L0@24576 (64x128), L1@40960 (128x128), L2@73728 (192x128)
__device__ __align__(16) unsigned short g_Bp[122880];
__device__ int   g_cnt[NN];
__device__ int   g_rowptr[NN];
__device__ int   g_cursor[NN];
__device__ int   g_csr_src[EE];
__device__ float g_invdeg[NN];
__device__ int   g_part[256];
__device__ float g_s[256];

__device__ __forceinline__ uint32_t packbf(float x, float y) {
    return ((uint32_t)__bfloat16_as_ushort(__float2bfloat16(y)) << 16) |
           __bfloat16_as_ushort(__float2bfloat16(x));
}

// ================= CSR build =================
__global__ void zero_kernel() {
    int i = blockIdx.x * blockDim.x + threadIdx.x;
    if (i < NN) g_cnt[i] = 0;
    if (i < 256) g_s[i] = 0.f;
}
__global__ void hist2_kernel(const int* __restrict__ ei) {
    int e = (blockIdx.x * blockDim.x + threadIdx.x) * 2;
    if (e < EE) {
        int2 d = *(const int2*)&ei[EE + e];
        atomicAdd(&g_cnt[d.x], 1);
        atomicAdd(&g_cnt[d.y], 1);
    }
}
__global__ void part_kernel() {
    __shared__ int s[256];
    int t = threadIdx.x, b = blockIdx.x;
    int i = b * 256 + t;
    int v = (i < NN) ? g_cnt[i] : 0;
    s[t] = v;
    __syncthreads();
    for (int off = 128; off > 0; off >>= 1) {
        if (t < off) s[t] += s[t + off];
        __syncthreads();
    }
    if (t == 0) g_part[b] = s[0];
}
__global__ void fill2_kernel(int nb) {
    __shared__ int sp[256];
    __shared__ int sl[256];
    int t = threadIdx.x, b = blockIdx.x;
    sp[t] = (t < nb) ? g_part[t] : 0;
    __syncthreads();
    for (int off = 1; off < 256; off <<= 1) {
        int a = (t >= off) ? sp[t - off] : 0;
        __syncthreads();
        sp[t] += a;
        __syncthreads();
    }
    int blockbase = (b == 0) ? 0 : sp[b - 1];
    int i = b * 256 + t;
    int v = (i < NN) ? g_cnt[i] : 0;
    sl[t] = v;
    __syncthreads();
    for (int off = 1; off < 256; off <<= 1) {
        int a = (t >= off) ? sl[t - off] : 0;
        __syncthreads();
        sl[t] += a;
        __syncthreads();
    }
    if (i < NN) {
        int base = blockbase + sl[t] - v;
        g_rowptr[i] = base;
        g_cursor[i] = base;
        g_invdeg[i] = 1.0f / (float)(v > 1 ? v : 1);
    }
}
__global__ void scatter2_kernel(const int* __restrict__ ei) {
    int e = (blockIdx.x * blockDim.x + threadIdx.x) * 2;
    if (e < EE) {
        int2 s = *(const int2*)&ei[e];
        int2 d = *(const int2*)&ei[EE + e];
        int p0 = atomicAdd(&g_cursor[d.x], 1);
        g_csr_src[p0] = s.x;
        int p1 = atomicAdd(&g_cursor[d.y], 1);
        g_csr_src[p1] = s.y;
    }
}

// ================= pack ALL weight images (hi/lo uint4 frags) =================
__device__ __forceinline__ void pack_one(float w, int k, int n, int NTILE, int off_us) {
    int kc = k >> 4, kin = k & 15, nc = n >> 3, nin = n & 7;
    int lane = nin * 4 + ((kin & 7) >> 1);
    int reg = kin >> 3, half = kin & 1;
    int base = ((kc * (NTILE >> 3) + nc) * 32 + lane) * 4;  // u32 idx of frag
    __nv_bfloat16 hi = __float2bfloat16(w);
    __nv_bfloat16 lo = __float2bfloat16(w - __bfloat162float(hi));
    g_Bp[off_us + (base + reg) * 2 + half]     = __bfloat16_as_ushort(hi);
    g_Bp[off_us + (base + 2 + reg) * 2 + half] = __bfloat16_as_ushort(lo);
}
__global__ void packAll_kernel(const float* __restrict__ pre_w1, const float* __restrict__ pre_w2,
                               const float* __restrict__ wl0, const float* __restrict__ wr0,
                               const float* __restrict__ wl1, const float* __restrict__ wr1,
                               const float* __restrict__ wl2, const float* __restrict__ wr2,
                               const float* __restrict__ skip) {
    int idx = blockIdx.x * blockDim.x + threadIdx.x;
    if (idx < 8192) {  // pre1: K=128, N=64
        int k = idx >> 6, n = idx & 63;
        pack_one(pre_w1[k * 64 + n], k, n, 64, 0);
    } else if (idx < 12288) {  // pre2: K=64, N=64
        int j = idx - 8192;
        int k = j >> 6, n = j & 63;
        pack_one(pre_w2[k * 64 + n], k, n, 64, 16384);
    } else if (idx < 20480) {  // L0: K=64, N=128
        int j = idx - 12288;
        int k = j >> 7, n = j & 127;
        float g = 1.f / (1.f + expf(-skip[0]));
        float w = ((n < 64) ? wl0[k * 64 + n] : wr0[k * 64 + (n - 64)]) * g;
        pack_one(w, k, n, 128, 24576);
    } else if (idx < 36864) {  // L1: K=128, N=128
        int j = idx - 20480;
        int k = j >> 7, n = j & 127;
        float g = 1.f / (1.f + expf(-skip[3 + (k >> 6)]));
        float w = ((n < 64) ? wl1[k * 64 + n] : wr1[k * 64 + (n - 64)]) * g;
        pack_one(w, k, n, 128, 40960);
    } else if (idx < 61440) {  // L2: K=192, N=128
        int j = idx - 36864;
        int k = j >> 7, n = j & 127;
        float g = 1.f / (1.f + expf(-skip[6 + (k >> 6)]));
        float w = ((n < 64) ? wl2[k * 64 + n] : wr2[k * 64 + (n - 64)]) * g;
        pack_one(w, k, n, 128, 73728);
    }
}

// ================= HMMA helper =================
__device__ __forceinline__ void mma16816(float* acc, const uint32_t* a,
                                         uint32_t b0, uint32_t b1) {
    asm volatile(
        "mma.sync.aligned.m16n8k16.row.col.f32.bf16.bf16.f32 "
        "{%0,%1,%2,%3}, {%4,%5,%6,%7}, {%8,%9}, {%0,%1,%2,%3};"
        : "+f"(acc[0]), "+f"(acc[1]), "+f"(acc[2]), "+f"(acc[3])
        : "r"(a[0]), "r"(a[1]), "r"(a[2]), "r"(a[3]), "r"(b0), "r"(b1));
}

#define SMS 33  // smem row stride in u32 (32 data + 1 pad)

// ================= fused pre-MLP + L0 GEMM (bf16 A, split W) =================
__global__ void __launch_bounds__(256) fused_pre_kernel(
    const float* __restrict__ X,
    const uint4* __restrict__ B1, const float* __restrict__ b1v,
    const uint4* __restrict__ B2, const float* __restrict__ b2v,
    const uint4* __restrict__ B0,
    uint32_t* __restrict__ embp, uint32_t* __restrict__ yb, int M) {
    __shared__ uint32_t t_s[128 * SMS];
    __shared__ uint32_t x_s[128 * SMS];
    const int tid = threadIdx.x;
    const int wid = tid >> 5, lane = tid & 31;
    const int wm = wid >> 1, wn = wid & 1;
    const int q = lane & 3, tq = lane >> 2;
    const int lr0 = wm * 32 + tq;
    const int gb = blockIdx.x * 128;

    // ---------- phase 1: t = relu(X@W1+b1), K=128, N=64 ----------
    {
        float acc[2][4][4];
#pragma unroll
        for (int m = 0; m < 2; m++)
#pragma unroll
            for (int i = 0; i < 4; i++)
#pragma unroll
                for (int j = 0; j < 4; j++) acc[m][i][j] = 0.f;
        for (int kc = 0; kc < 8; kc++) {
            const int c0 = kc * 16 + 2 * q;
            uint32_t a[2][4];
#pragma unroll
            for (int mf = 0; mf < 2; mf++) {
                int ra = gb + lr0 + mf * 16, rc = ra + 8;
                float2 v00 = make_float2(0.f, 0.f), v01 = v00, v10 = v00, v11 = v00;
                if (ra < M) {
                    v00 = *(const float2*)&X[(size_t)ra * 128 + c0];
                    v01 = *(const float2*)&X[(size_t)ra * 128 + c0 + 8];
                }
                if (rc < M) {
                    v10 = *(const float2*)&X[(size_t)rc * 128 + c0];
                    v11 = *(const float2*)&X[(size_t)rc * 128 + c0 + 8];
                }
                a[mf][0] = packbf(v00.x, v00.y);
                a[mf][1] = packbf(v10.x, v10.y);
                a[mf][2] = packbf(v01.x, v01.y);
                a[mf][3] = packbf(v11.x, v11.y);
            }
            const uint4* bp = B1 + (size_t)(kc * 8 + wn * 4) * 32 + lane;
#pragma unroll
            for (int nc = 0; nc < 4; nc++) {
                uint4 b = bp[nc * 32];
                mma16816(acc[0][nc], a[0], b.x, b.y);
                mma16816(acc[0][nc], a[0], b.z, b.w);
                mma16816(acc[1][nc], a[1], b.x, b.y);
                mma16816(acc[1][nc], a[1], b.z, b.w);
            }
        }
#pragma unroll
        for (int nc = 0; nc < 4; nc++) {
            int col = wn * 32 + nc * 8 + 2 * q;
            float bb0 = b1v[col], bb1 = b1v[col + 1];
#pragma unroll
            for (int mf = 0; mf < 2; mf++) {
                int la = lr0 + mf * 16, lc = la + 8;
                t_s[la * SMS + (col >> 1)] =
                    packbf(fmaxf(acc[mf][nc][0] + bb0, 0.f), fmaxf(acc[mf][nc][1] + bb1, 0.f));
                t_s[lc * SMS + (col >> 1)] =
                    packbf(fmaxf(acc[mf][nc][2] + bb0, 0.f), fmaxf(acc[mf][nc][3] + bb1, 0.f));
            }
        }
    }
    __syncthreads();

    // ---------- phase 2: x = t@W2+b2, K=64, N=64 ----------
    {
        float acc[2][4][4];
#pragma unroll
        for (int m = 0; m < 2; m++)
#pragma unroll
            for (int i = 0; i < 4; i++)
#pragma unroll
                for (int j = 0; j < 4; j++) acc[m][i][j] = 0.f;
        for (int kc = 0; kc < 4; kc++) {
            const int ci = kc * 8 + q;  // u32 index of k-pair
            uint32_t a[2][4];
#pragma unroll
            for (int mf = 0; mf < 2; mf++) {
                int la = lr0 + mf * 16, lc = la + 8;
                a[mf][0] = t_s[la * SMS + ci];
                a[mf][1] = t_s[lc * SMS + ci];
                a[mf][2] = t_s[la * SMS + ci + 4];
                a[mf][3] = t_s[lc * SMS + ci + 4];
            }
            const uint4* bp = B2 + (size_t)(kc * 8 + wn * 4) * 32 + lane;
#pragma unroll
            for (int nc = 0; nc < 4; nc++) {
                uint4 b = bp[nc * 32];
                mma16816(acc[0][nc], a[0], b.x, b.y);
                mma16816(acc[0][nc], a[0], b.z, b.w);
                mma16816(acc[1][nc], a[1], b.x, b.y);
                mma16816(acc[1][nc], a[1], b.z, b.w);
            }
        }
        __syncthreads();
#pragma unroll
        for (int nc = 0; nc < 4; nc++) {
            int col = wn * 32 + nc * 8 + 2 * q;
            float bb0 = b2v[col], bb1 = b2v[col + 1];
#pragma unroll
            for (int mf = 0; mf < 2; mf++) {
                int la = lr0 + mf * 16, lc = la + 8;
                uint32_t p0 = packbf(acc[mf][nc][0] + bb0, acc[mf][nc][1] + bb1);
                uint32_t p1 = packbf(acc[mf][nc][2] + bb0, acc[mf][nc][3] + bb1);
                x_s[la * SMS + (col >> 1)] = p0;
                if (gb + la < M) embp[(size_t)(gb + la) * 128 + (col >> 1)] = p0;
                x_s[lc * SMS + (col >> 1)] = p1;
                if (gb + lc < M) embp[(size_t)(gb + lc) * 128 + (col >> 1)] = p1;
            }
        }
    }
    __syncthreads();

    // ---------- phase 3: y0|r0 = x@W0g, K=64, N=128 ----------
    {
        float acc[2][8][4];
#pragma unroll
        for (int m = 0; m < 2; m++)
#pragma unroll
            for (int i = 0; i < 8; i++)
#pragma unroll
                for (int j = 0; j < 4; j++) acc[m][i][j] = 0.f;
        for (int kc = 0; kc < 4; kc++) {
            const int ci = kc * 8 + q;
            uint32_t a[2][4];
#pragma unroll
            for (int mf = 0; mf < 2; mf++) {
                int la = lr0 + mf * 16, lc = la + 8;
                a[mf][0] = x_s[la * SMS + ci];
                a[mf][1] = x_s[lc * SMS + ci];
                a[mf][2] = x_s[la * SMS + ci + 4];
                a[mf][3] = x_s[lc * SMS + ci + 4];
            }
            const uint4* bp = B0 + (size_t)(kc * 16 + wn * 8) * 32 + lane;
#pragma unroll
            for (int nc = 0; nc < 8; nc++) {
                uint4 b = bp[nc * 32];
                mma16816(acc[0][nc], a[0], b.x, b.y);
                mma16816(acc[0][nc], a[0], b.z, b.w);
                mma16816(acc[1][nc], a[1], b.x, b.y);
                mma16816(acc[1][nc], a[1], b.z, b.w);
            }
        }
#pragma unroll
        for (int nc = 0; nc < 8; nc++) {
            int col = wn * 64 + nc * 8 + 2 * q;
#pragma unroll
            for (int mf = 0; mf < 2; mf++) {
                int ra = gb + lr0 + mf * 16, rc = ra + 8;
                if (ra < M) yb[(size_t)ra * 64 + (col >> 1)] =
                    packbf(acc[mf][nc][0], acc[mf][nc][1]);
                if (rc < M) yb[(size_t)rc * 64 + (col >> 1)] =
                    packbf(acc[mf][nc][2], acc[mf][nc][3]);
            }
        }
    }
}

// ================= standalone GEMM (layers 1,2): bf16 A, split W ====
template <int NTILE>
__global__ void __launch_bounds__(256) mma_gemm6(
    const uint32_t* __restrict__ Ap, int lda, int K,
    const uint4* __restrict__ Bp,
    uint32_t* __restrict__ Cout, int ldc, int M) {
    constexpr int NFRAG = NTILE / 8;
    constexpr int WNF = NFRAG / 2;
    const int tid = threadIdx.x;
    const int wid = tid >> 5, lane = tid & 31;
    const int wm = wid >> 1, wn = wid & 1;
    const int q = lane & 3, tq = lane >> 2;
    const int rb = blockIdx.x * 128 + wm * 32 + tq;

    float acc[2][WNF][4];
#pragma unroll
    for (int m = 0; m < 2; m++)
#pragma unroll
        for (int i = 0; i < WNF; i++)
#pragma unroll
            for (int j = 0; j < 4; j++) acc[m][i][j] = 0.f;

    for (int kc = 0; kc < K / 16; kc++) {
        const int ci = kc * 8 + q;
        uint32_t a[2][4];
#pragma unroll
        for (int mf = 0; mf < 2; mf++) {
            int ra = rb + mf * 16, rc = ra + 8;
            uint32_t a0 = 0, a1 = 0, a2 = 0, a3 = 0;
            if (ra < M) {
                a0 = Ap[(size_t)ra * lda + ci];
                a2 = Ap[(size_t)ra * lda + ci + 4];
            }
            if (rc < M) {
                a1 = Ap[(size_t)rc * lda + ci];
                a3 = Ap[(size_t)rc * lda + ci + 4];
            }
            a[mf][0] = a0; a[mf][1] = a1; a[mf][2] = a2; a[mf][3] = a3;
        }
        const uint4* bp = Bp + (size_t)(kc * NFRAG + wn * WNF) * 32 + lane;
#pragma unroll
        for (int nc = 0; nc < WNF; nc++) {
            uint4 b = bp[nc * 32];
            mma16816(acc[0][nc], a[0], b.x, b.y);
            mma16816(acc[0][nc], a[0], b.z, b.w);
            mma16816(acc[1][nc], a[1], b.x, b.y);
            mma16816(acc[1][nc], a[1], b.z, b.w);
        }
    }

#pragma unroll
    for (int nc = 0; nc < WNF; nc++) {
        int col = wn * (NTILE / 2) + nc * 8 + 2 * q;
#pragma unroll
        for (int mf = 0; mf < 2; mf++) {
            int ra = rb + mf * 16, rc = ra + 8;
            if (ra < M) Cout[(size_t)ra * ldc + (col >> 1)] =
                packbf(acc[mf][nc][0], acc[mf][nc][1]);
            if (rc < M) Cout[(size_t)rc * ldc + (col >> 1)] =
                packbf(acc[mf][nc][2], acc[mf][nc][3]);
        }
    }
}

// ================= aggregation: one warp per node ==========
__global__ void agg_kernel(const float* __restrict__ bl, int outc) {
    int gw = (blockIdx.x * blockDim.x + threadIdx.x) >> 5;
    int lane = threadIdx.x & 31;
    if (gw >= NN) return;
    const int n = gw;
    const int beg = g_rowptr[n], cnt = g_cnt[n];
    const uint32_t* __restrict__ yb = g_yb;
    float sx = 0.f, sy = 0.f;
    for (int k = 0; k < cnt; k++) {
        int src = g_csr_src[beg + k];
        uint32_t v = yb[(size_t)src * 64 + lane];
        sx += __uint_as_float(v << 16);
        sy += __uint_as_float(v & 0xFFFF0000u);
    }
    float inv = g_invdeg[n];
    uint32_t rv = yb[(size_t)n * 64 + 32 + lane];
    float r0 = __uint_as_float(rv << 16);
    float r1 = __uint_as_float(rv & 0xFFFF0000u);
    float h0 = fmaxf(sx * inv + bl[2 * lane] + r0, 0.f);
    float h1 = fmaxf(sy * inv + bl[2 * lane + 1] + r1, 0.f);
    g_embp[(size_t)n * 128 + outc + lane] = packbf(h0, h1);
}

// ================= column sum over packed emb + post mlp =================
__global__ void colsum_kernel() {
    int t = threadIdx.x;  // 128 threads: col pair (2t, 2t+1)
    int per = (NN + gridDim.x - 1) / gridDim.x;
    int n0 = blockIdx.x * per;
    int n1 = n0 + per;
    if (n1 > NN) n1 = NN;
    float s0 = 0.f, s1 = 0.f;
    for (int n = n0; n < n1; n++) {
        uint32_t w = g_embp[(size_t)n * 128 + t];
        s0 += __uint_as_float(w << 16);
        s1 += __uint_as_float(w & 0xFFFF0000u);
    }
    atomicAdd(&g_s[2 * t], s0);
    atomicAdd(&g_s[2 * t + 1], s1);
}
__global__ void post_kernel(const float* __restrict__ w1, const float* __restrict__ b1,
                            const float* __restrict__ w2, const float* __restrict__ b2,
                            const float* __restrict__ w3, const float* __restrict__ b3,
                            const float* __restrict__ w4, const float* __restrict__ b4,
                            float* __restrict__ out) {
    __shared__ float s1[64], s2[64], s3[256];
    int t = threadIdx.x;
    if (t < 64) {
        float a = b1[t];
        for (int k = 0; k < 256; k++) a += g_s[k] * w1[k * 64 + t];
        s1[t] = (a > 0.f) ? a : 0.1f * a;
    }
    __syncthreads();
    if (t < 64) {
        float a = b2[t];
        for (int k = 0; k < 64; k++) a += s1[k] * w2[k * 64 + t];
        s2[t] = fmaxf(a, 0.f);
    }
    __syncthreads();
    {
        float a = b3[t];
        for (int k = 0; k < 64; k++) a += s2[k] * w3[k * 256 + t];
        s3[t] = fmaxf(a, 0.f);
    }
    __syncthreads();
    if (t < 64) {
        float a = b4[t];
        for (int k = 0; k < 256; k++) a += s3[k] * w4[k * 64 + t];
        out[t] = a;
    }
}

// ================= launch =================
extern "C" void kernel_launch(void* const* d_in, const int* in_sizes, int n_in,
                              void* d_out, int out_size) {
    const float* node_features = (const float*)d_in[0];
    const int*   edge_index    = (const int*)d_in[1];
    const float* pre_w1 = (const float*)d_in[2];
    const float* pre_b1 = (const float*)d_in[3];
    const float* pre_w2 = (const float*)d_in[4];
    const float* pre_b2 = (const float*)d_in[5];
    const float* skip   = (const float*)d_in[6];
    const float* wl[3] = {(const float*)d_in[7], (const float*)d_in[10], (const float*)d_in[13]};
    const float* bl[3] = {(const float*)d_in[8], (const float*)d_in[11], (const float*)d_in[14]};
    const float* wr[3] = {(const float*)d_in[9], (const float*)d_in[12], (const float*)d_in[15]};
    const float* post_w1 = (const float*)d_in[16];
    const float* post_b1 = (const float*)d_in[17];
    const float* post_w2 = (const float*)d_in[18];
    const float* post_b2 = (const float*)d_in[19];
    const float* post_w3 = (const float*)d_in[20];
    const float* post_b3 = (const float*)d_in[21];
    const float* post_w4 = (const float*)d_in[22];
    const float* post_b4 = (const float*)d_in[23];
    float* out = (float*)d_out;

    uint32_t *p_embp, *p_yb;
    unsigned short* p_Bp;
    cudaGetSymbolAddress((void**)&p_embp, g_embp);
    cudaGetSymbolAddress((void**)&p_yb, g_yb);
    cudaGetSymbolAddress((void**)&p_Bp, g_Bp);

    const int NB = (NN + 255) / 256;  // 196
    const int MB = (NN + 127) / 128;  // 391

    // CSR build
    zero_kernel<<<NB, 256>>>();
    hist2_kernel<<<(EE / 2 + 255) / 256, 256>>>(edge_index);
    part_kernel<<<NB, 256>>>();
    fill2_kernel<<<NB, 256>>>(NB);
    scatter2_kernel<<<(EE / 2 + 255) / 256, 256>>>(edge_index);

    // pack weights, fused pre-MLP + L0
    packAll_kernel<<<(61440 + 255) / 256, 256>>>(pre_w1, pre_w2, wl[0], wr[0], wl[1], wr[1],
                                                 wl[2], wr[2], skip);
    fused_pre_kernel<<<MB, 256>>>(
        node_features, (const uint4*)(p_Bp), pre_b1,
        (const uint4*)(p_Bp + 16384), pre_b2,
        (const uint4*)(p_Bp + 24576), p_embp, p_yb, NN);

    agg_kernel<<<(NN * 32 + 255) / 256, 256>>>(bl[0], 32);

    mma_gemm6<128><<<MB, 256>>>(p_embp, 128, 128, (const uint4*)(p_Bp + 40960),
                                p_yb, 64, NN);
    agg_kernel<<<(NN * 32 + 255) / 256, 256>>>(bl[1], 64);

    mma_gemm6<128><<<MB, 256>>>(p_embp, 128, 192, (const uint4*)(p_Bp + 73728),
                                p_yb, 64, NN);
    agg_kernel<<<(NN * 32 + 255) / 256, 256>>>(bl[2], 96);

    colsum_kernel<<<256, 128>>>();
    post_kernel<<<1, 256>>>(post_w1, post_b1, post_w2, post_b2, post_w3, post_b3,
                            post_w4, post_b4, out);
}

// round 14
// speedup vs baseline: 2.2766x; 1.0975x over previous
#include <cuda_runtime.h>
#include <cuda_bf16.h>
#include <math.h>
#include <stdint.h>

#define NN 50000
#define EE 800000

// ================= scratch (device globals) =================
__device__ uint32_t g_embp[(size_t)NN * 128];  // [x|h1|h2|h3] packed bf16x2 (2 cols/u32)
__device__ uint32_t g_yb[(size_t)NN * 64];     // per-layer [y | r] packed bf16x2
// packed hi/lo weight images, uint4 frags [bh0,bh1,bl0,bl1] (ushort units):
//  pre1@0 (128x64), pre2@16384 (64x64), L0@24576 (64x128), L1@40960 (128x128), L2@73728 (192x128)
__device__ __align__(16) unsigned short g_Bp[122880];
__device__ int   g_cnt[NN];
__device__ int   g_rowptr[NN];
__device__ int   g_cursor[NN];
__device__ int   g_csr_src[EE];
__device__ float g_invdeg[NN];
__device__ int   g_part[256];
__device__ float g_s[256];

__device__ __forceinline__ uint32_t packbf(float x, float y) {
    return ((uint32_t)__bfloat16_as_ushort(__float2bfloat16(y)) << 16) |
           __bfloat16_as_ushort(__float2bfloat16(x));
}
__device__ __forceinline__ float bflo(uint32_t v) { return __uint_as_float(v << 16); }
__device__ __forceinline__ float bfhi(uint32_t v) { return __uint_as_float(v & 0xFFFF0000u); }

// ================= CSR build =================
__global__ void zero_kernel() {
    int i = blockIdx.x * blockDim.x + threadIdx.x;
    if (i < NN) g_cnt[i] = 0;
    if (i < 256) g_s[i] = 0.f;
}
__global__ void hist2_kernel(const int* __restrict__ ei) {
    int e = (blockIdx.x * blockDim.x + threadIdx.x) * 2;
    if (e < EE) {
        int2 d = *(const int2*)&ei[EE + e];
        atomicAdd(&g_cnt[d.x], 1);
        atomicAdd(&g_cnt[d.y], 1);
    }
}
__global__ void part_kernel() {
    __shared__ int s[256];
    int t = threadIdx.x, b = blockIdx.x;
    int i = b * 256 + t;
    int v = (i < NN) ? g_cnt[i] : 0;
    s[t] = v;
    __syncthreads();
    for (int off = 128; off > 0; off >>= 1) {
        if (t < off) s[t] += s[t + off];
        __syncthreads();
    }
    if (t == 0) g_part[b] = s[0];
}
__global__ void fill2_kernel(int nb) {
    __shared__ int sp[256];
    __shared__ int sl[256];
    int t = threadIdx.x, b = blockIdx.x;
    sp[t] = (t < nb) ? g_part[t] : 0;
    __syncthreads();
    for (int off = 1; off < 256; off <<= 1) {
        int a = (t >= off) ? sp[t - off] : 0;
        __syncthreads();
        sp[t] += a;
        __syncthreads();
    }
    int blockbase = (b == 0) ? 0 : sp[b - 1];
    int i = b * 256 + t;
    int v = (i < NN) ? g_cnt[i] : 0;
    sl[t] = v;
    __syncthreads();
    for (int off = 1; off < 256; off <<= 1) {
        int a = (t >= off) ? sl[t - off] : 0;
        __syncthreads();
        sl[t] += a;
        __syncthreads();
    }
    if (i < NN) {
        int base = blockbase + sl[t] - v;
        g_rowptr[i] = base;
        g_cursor[i] = base;
        g_invdeg[i] = 1.0f / (float)(v > 1 ? v : 1);
    }
}
__global__ void scatter2_kernel(const int* __restrict__ ei) {
    int e = (blockIdx.x * blockDim.x + threadIdx.x) * 2;
    if (e < EE) {
        int2 s = *(const int2*)&ei[e];
        int2 d = *(const int2*)&ei[EE + e];
        int p0 = atomicAdd(&g_cursor[d.x], 1);
        g_csr_src[p0] = s.x;
        int p1 = atomicAdd(&g_cursor[d.y], 1);
        g_csr_src[p1] = s.y;
    }
}

// ================= pack ALL weight images (hi/lo uint4 frags) =================
__device__ __forceinline__ void pack_one(float w, int k, int n, int NTILE, int off_us) {
    int kc = k >> 4, kin = k & 15, nc = n >> 3, nin = n & 7;
    int lane = nin * 4 + ((kin & 7) >> 1);
    int reg = kin >> 3, half = kin & 1;
    int base = ((kc * (NTILE >> 3) + nc) * 32 + lane) * 4;
    __nv_bfloat16 hi = __float2bfloat16(w);
    __nv_bfloat16 lo = __float2bfloat16(w - __bfloat162float(hi));
    g_Bp[off_us + (base + reg) * 2 + half]     = __bfloat16_as_ushort(hi);
    g_Bp[off_us + (base + 2 + reg) * 2 + half] = __bfloat16_as_ushort(lo);
}
__global__ void packAll_kernel(const float* __restrict__ pre_w1, const float* __restrict__ pre_w2,
                               const float* __restrict__ wl0, const float* __restrict__ wr0,
                               const float* __restrict__ wl1, const float* __restrict__ wr1,
                               const float* __restrict__ wl2, const float* __restrict__ wr2,
                               const float* __restrict__ skip) {
    int idx = blockIdx.x * blockDim.x + threadIdx.x;
    if (idx < 8192) {
        int k = idx >> 6, n = idx & 63;
        pack_one(pre_w1[k * 64 + n], k, n, 64, 0);
    } else if (idx < 12288) {
        int j = idx - 8192;
        int k = j >> 6, n = j & 63;
        pack_one(pre_w2[k * 64 + n], k, n, 64, 16384);
    } else if (idx < 20480) {
        int j = idx - 12288;
        int k = j >> 7, n = j & 127;
        float g = 1.f / (1.f + expf(-skip[0]));
        float w = ((n < 64) ? wl0[k * 64 + n] : wr0[k * 64 + (n - 64)]) * g;
        pack_one(w, k, n, 128, 24576);
    } else if (idx < 36864) {
        int j = idx - 20480;
        int k = j >> 7, n = j & 127;
        float g = 1.f / (1.f + expf(-skip[3 + (k >> 6)]));
        float w = ((n < 64) ? wl1[k * 64 + n] : wr1[k * 64 + (n - 64)]) * g;
        pack_one(w, k, n, 128, 40960);
    } else if (idx < 61440) {
        int j = idx - 36864;
        int k = j >> 7, n = j & 127;
        float g = 1.f / (1.f + expf(-skip[6 + (k >> 6)]));
        float w = ((n < 64) ? wl2[k * 64 + n] : wr2[k * 64 + (n - 64)]) * g;
        pack_one(w, k, n, 128, 73728);
    }
}

// ================= HMMA helper =================
__device__ __forceinline__ void mma16816(float* acc, const uint32_t* a,
                                         uint32_t b0, uint32_t b1) {
    asm volatile(
        "mma.sync.aligned.m16n8k16.row.col.f32.bf16.bf16.f32 "
        "{%0,%1,%2,%3}, {%4,%5,%6,%7}, {%8,%9}, {%0,%1,%2,%3};"
        : "+f"(acc[0]), "+f"(acc[1]), "+f"(acc[2]), "+f"(acc[3])
        : "r"(a[0]), "r"(a[1]), "r"(a[2]), "r"(a[3]), "r"(b0), "r"(b1));
}

#define SMS 33  // smem row stride in u32 (32 data + 1 pad)

// ================= fused pre-MLP + L0 GEMM (bf16 A, split W) =================
__global__ void __launch_bounds__(256) fused_pre_kernel(
    const float* __restrict__ X,
    const uint4* __restrict__ B1, const float* __restrict__ b1v,
    const uint4* __restrict__ B2, const float* __restrict__ b2v,
    const uint4* __restrict__ B0,
    uint32_t* __restrict__ embp, uint32_t* __restrict__ yb, int M) {
    __shared__ uint32_t t_s[128 * SMS];
    __shared__ uint32_t x_s[128 * SMS];
    const int tid = threadIdx.x;
    const int wid = tid >> 5, lane = tid & 31;
    const int wm = wid >> 1, wn = wid & 1;
    const int q = lane & 3, tq = lane >> 2;
    const int lr0 = wm * 32 + tq;
    const int gb = blockIdx.x * 128;

    // ---------- phase 1: t = relu(X@W1+b1), K=128, N=64 ----------
    {
        float acc[2][4][4];
#pragma unroll
        for (int m = 0; m < 2; m++)
#pragma unroll
            for (int i = 0; i < 4; i++)
#pragma unroll
                for (int j = 0; j < 4; j++) acc[m][i][j] = 0.f;
        for (int kc = 0; kc < 8; kc++) {
            const int c0 = kc * 16 + 2 * q;
            uint32_t a[2][4];
#pragma unroll
            for (int mf = 0; mf < 2; mf++) {
                int ra = gb + lr0 + mf * 16, rc = ra + 8;
                float2 v00 = make_float2(0.f, 0.f), v01 = v00, v10 = v00, v11 = v00;
                if (ra < M) {
                    v00 = *(const float2*)&X[(size_t)ra * 128 + c0];
                    v01 = *(const float2*)&X[(size_t)ra * 128 + c0 + 8];
                }
                if (rc < M) {
                    v10 = *(const float2*)&X[(size_t)rc * 128 + c0];
                    v11 = *(const float2*)&X[(size_t)rc * 128 + c0 + 8];
                }
                a[mf][0] = packbf(v00.x, v00.y);
                a[mf][1] = packbf(v10.x, v10.y);
                a[mf][2] = packbf(v01.x, v01.y);
                a[mf][3] = packbf(v11.x, v11.y);
            }
            const uint4* bp = B1 + (size_t)(kc * 8 + wn * 4) * 32 + lane;
#pragma unroll
            for (int nc = 0; nc < 4; nc++) {
                uint4 b = bp[nc * 32];
                mma16816(acc[0][nc], a[0], b.x, b.y);
                mma16816(acc[0][nc], a[0], b.z, b.w);
                mma16816(acc[1][nc], a[1], b.x, b.y);
                mma16816(acc[1][nc], a[1], b.z, b.w);
            }
        }
#pragma unroll
        for (int nc = 0; nc < 4; nc++) {
            int col = wn * 32 + nc * 8 + 2 * q;
            float bb0 = b1v[col], bb1 = b1v[col + 1];
#pragma unroll
            for (int mf = 0; mf < 2; mf++) {
                int la = lr0 + mf * 16, lc = la + 8;
                t_s[la * SMS + (col >> 1)] =
                    packbf(fmaxf(acc[mf][nc][0] + bb0, 0.f), fmaxf(acc[mf][nc][1] + bb1, 0.f));
                t_s[lc * SMS + (col >> 1)] =
                    packbf(fmaxf(acc[mf][nc][2] + bb0, 0.f), fmaxf(acc[mf][nc][3] + bb1, 0.f));
            }
        }
    }
    __syncthreads();

    // ---------- phase 2: x = t@W2+b2, K=64, N=64 ----------
    {
        float acc[2][4][4];
#pragma unroll
        for (int m = 0; m < 2; m++)
#pragma unroll
            for (int i = 0; i < 4; i++)
#pragma unroll
                for (int j = 0; j < 4; j++) acc[m][i][j] = 0.f;
        for (int kc = 0; kc < 4; kc++) {
            const int ci = kc * 8 + q;
            uint32_t a[2][4];
#pragma unroll
            for (int mf = 0; mf < 2; mf++) {
                int la = lr0 + mf * 16, lc = la + 8;
                a[mf][0] = t_s[la * SMS + ci];
                a[mf][1] = t_s[lc * SMS + ci];
                a[mf][2] = t_s[la * SMS + ci + 4];
                a[mf][3] = t_s[lc * SMS + ci + 4];
            }
            const uint4* bp = B2 + (size_t)(kc * 8 + wn * 4) * 32 + lane;
#pragma unroll
            for (int nc = 0; nc < 4; nc++) {
                uint4 b = bp[nc * 32];
                mma16816(acc[0][nc], a[0], b.x, b.y);
                mma16816(acc[0][nc], a[0], b.z, b.w);
                mma16816(acc[1][nc], a[1], b.x, b.y);
                mma16816(acc[1][nc], a[1], b.z, b.w);
            }
        }
        __syncthreads();
#pragma unroll
        for (int nc = 0; nc < 4; nc++) {
            int col = wn * 32 + nc * 8 + 2 * q;
            float bb0 = b2v[col], bb1 = b2v[col + 1];
#pragma unroll
            for (int mf = 0; mf < 2; mf++) {
                int la = lr0 + mf * 16, lc = la + 8;
                uint32_t p0 = packbf(acc[mf][nc][0] + bb0, acc[mf][nc][1] + bb1);
                uint32_t p1 = packbf(acc[mf][nc][2] + bb0, acc[mf][nc][3] + bb1);
                x_s[la * SMS + (col >> 1)] = p0;
                if (gb + la < M) embp[(size_t)(gb + la) * 128 + (col >> 1)] = p0;
                x_s[lc * SMS + (col >> 1)] = p1;
                if (gb + lc < M) embp[(size_t)(gb + lc) * 128 + (col >> 1)] = p1;
            }
        }
    }
    __syncthreads();

    // ---------- phase 3: y0|r0 = x@W0g, K=64, N=128 ----------
    {
        float acc[2][8][4];
#pragma unroll
        for (int m = 0; m < 2; m++)
#pragma unroll
            for (int i = 0; i < 8; i++)
#pragma unroll
                for (int j = 0; j < 4; j++) acc[m][i][j] = 0.f;
        for (int kc = 0; kc < 4; kc++) {
            const int ci = kc * 8 + q;
            uint32_t a[2][4];
#pragma unroll
            for (int mf = 0; mf < 2; mf++) {
                int la = lr0 + mf * 16, lc = la + 8;
                a[mf][0] = x_s[la * SMS + ci];
                a[mf][1] = x_s[lc * SMS + ci];
                a[mf][2] = x_s[la * SMS + ci + 4];
                a[mf][3] = x_s[lc * SMS + ci + 4];
            }
            const uint4* bp = B0 + (size_t)(kc * 16 + wn * 8) * 32 + lane;
#pragma unroll
            for (int nc = 0; nc < 8; nc++) {
                uint4 b = bp[nc * 32];
                mma16816(acc[0][nc], a[0], b.x, b.y);
                mma16816(acc[0][nc], a[0], b.z, b.w);
                mma16816(acc[1][nc], a[1], b.x, b.y);
                mma16816(acc[1][nc], a[1], b.z, b.w);
            }
        }
#pragma unroll
        for (int nc = 0; nc < 8; nc++) {
            int col = wn * 64 + nc * 8 + 2 * q;
#pragma unroll
            for (int mf = 0; mf < 2; mf++) {
                int ra = gb + lr0 + mf * 16, rc = ra + 8;
                if (ra < M) yb[(size_t)ra * 64 + (col >> 1)] =
                    packbf(acc[mf][nc][0], acc[mf][nc][1]);
                if (rc < M) yb[(size_t)rc * 64 + (col >> 1)] =
                    packbf(acc[mf][nc][2], acc[mf][nc][3]);
            }
        }
    }
}

// ================= standalone GEMM (layers 1,2): bf16 A, split W ====
template <int NTILE>
__global__ void __launch_bounds__(256) mma_gemm6(
    const uint32_t* __restrict__ Ap, int lda, int K,
    const uint4* __restrict__ Bp,
    uint32_t* __restrict__ Cout, int ldc, int M) {
    constexpr int NFRAG = NTILE / 8;
    constexpr int WNF = NFRAG / 2;
    const int tid = threadIdx.x;
    const int wid = tid >> 5, lane = tid & 31;
    const int wm = wid >> 1, wn = wid & 1;
    const int q = lane & 3, tq = lane >> 2;
    const int rb = blockIdx.x * 128 + wm * 32 + tq;

    float acc[2][WNF][4];
#pragma unroll
    for (int m = 0; m < 2; m++)
#pragma unroll
        for (int i = 0; i < WNF; i++)
#pragma unroll
            for (int j = 0; j < 4; j++) acc[m][i][j] = 0.f;

    for (int kc = 0; kc < K / 16; kc++) {
        const int ci = kc * 8 + q;
        uint32_t a[2][4];
#pragma unroll
        for (int mf = 0; mf < 2; mf++) {
            int ra = rb + mf * 16, rc = ra + 8;
            uint32_t a0 = 0, a1 = 0, a2 = 0, a3 = 0;
            if (ra < M) {
                a0 = Ap[(size_t)ra * lda + ci];
                a2 = Ap[(size_t)ra * lda + ci + 4];
            }
            if (rc < M) {
                a1 = Ap[(size_t)rc * lda + ci];
                a3 = Ap[(size_t)rc * lda + ci + 4];
            }
            a[mf][0] = a0; a[mf][1] = a1; a[mf][2] = a2; a[mf][3] = a3;
        }
        const uint4* bp = Bp + (size_t)(kc * NFRAG + wn * WNF) * 32 + lane;
#pragma unroll
        for (int nc = 0; nc < WNF; nc++) {
            uint4 b = bp[nc * 32];
            mma16816(acc[0][nc], a[0], b.x, b.y);
            mma16816(acc[0][nc], a[0], b.z, b.w);
            mma16816(acc[1][nc], a[1], b.x, b.y);
            mma16816(acc[1][nc], a[1], b.z, b.w);
        }
    }

#pragma unroll
    for (int nc = 0; nc < WNF; nc++) {
        int col = wn * (NTILE / 2) + nc * 8 + 2 * q;
#pragma unroll
        for (int mf = 0; mf < 2; mf++) {
            int ra = rb + mf * 16, rc = ra + 8;
            if (ra < M) Cout[(size_t)ra * ldc + (col >> 1)] =
                packbf(acc[mf][nc][0], acc[mf][nc][1]);
            if (rc < M) Cout[(size_t)rc * ldc + (col >> 1)] =
                packbf(acc[mf][nc][2], acc[mf][nc][3]);
        }
    }
}

// ================= aggregation: 2 nodes per warp, 16 lanes/node ==========
__global__ void agg_kernel(const float* __restrict__ bl, int outc) {
    int gw = (blockIdx.x * blockDim.x + threadIdx.x) >> 5;
    int lane = threadIdx.x & 31;
    int half = lane >> 4;     // which node within the warp
    int h = lane & 15;        // lane within node (covers u32 cols 2h, 2h+1)
    int n = gw * 2 + half;
    if (n >= NN) return;
    const int beg = g_rowptr[n], cnt = g_cnt[n];
    const uint32_t* __restrict__ yb = g_yb;
    float sx0 = 0.f, sy0 = 0.f, sx1 = 0.f, sy1 = 0.f;
    for (int k = 0; k < cnt; k++) {
        int src = g_csr_src[beg + k];
        uint2 v = *(const uint2*)&yb[(size_t)src * 64 + 2 * h];
        sx0 += bflo(v.x); sy0 += bfhi(v.x);
        sx1 += bflo(v.y); sy1 += bfhi(v.y);
    }
    float inv = g_invdeg[n];
    uint2 rv = *(const uint2*)&yb[(size_t)n * 64 + 32 + 2 * h];
    float h0 = fmaxf(sx0 * inv + bl[4 * h]     + bflo(rv.x), 0.f);
    float h1 = fmaxf(sy0 * inv + bl[4 * h + 1] + bfhi(rv.x), 0.f);
    float h2 = fmaxf(sx1 * inv + bl[4 * h + 2] + bflo(rv.y), 0.f);
    float h3 = fmaxf(sy1 * inv + bl[4 * h + 3] + bfhi(rv.y), 0.f);
    *(uint2*)&g_embp[(size_t)n * 128 + outc + 2 * h] =
        make_uint2(packbf(h0, h1), packbf(h2, h3));
}

// ================= column sum over packed emb + post mlp =================
__global__ void colsum_kernel() {
    int t = threadIdx.x;  // 128 threads: col pair (2t, 2t+1)
    int per = (NN + gridDim.x - 1) / gridDim.x;
    int n0 = blockIdx.x * per;
    int n1 = n0 + per;
    if (n1 > NN) n1 = NN;
    float s0 = 0.f, s1 = 0.f;
    for (int n = n0; n < n1; n++) {
        uint32_t w = g_embp[(size_t)n * 128 + t];
        s0 += bflo(w);
        s1 += bfhi(w);
    }
    atomicAdd(&g_s[2 * t], s0);
    atomicAdd(&g_s[2 * t + 1], s1);
}
__global__ void post_kernel(const float* __restrict__ w1, const float* __restrict__ b1,
                            const float* __restrict__ w2, const float* __restrict__ b2,
                            const float* __restrict__ w3, const float* __restrict__ b3,
                            const float* __restrict__ w4, const float* __restrict__ b4,
                            float* __restrict__ out) {
    __shared__ float s1[64], s2[64], s3[256];
    int t = threadIdx.x;
    if (t < 64) {
        float a = b1[t];
        for (int k = 0; k < 256; k++) a += g_s[k] * w1[k * 64 + t];
        s1[t] = (a > 0.f) ? a : 0.1f * a;
    }
    __syncthreads();
    if (t < 64) {
        float a = b2[t];
        for (int k = 0; k < 64; k++) a += s1[k] * w2[k * 64 + t];
        s2[t] = fmaxf(a, 0.f);
    }
    __syncthreads();
    {
        float a = b3[t];
        for (int k = 0; k < 64; k++) a += s2[k] * w3[k * 256 + t];
        s3[t] = fmaxf(a, 0.f);
    }
    __syncthreads();
    if (t < 64) {
        float a = b4[t];
        for (int k = 0; k < 256; k++) a += s3[k] * w4[k * 64 + t];
        out[t] = a;
    }
}

// ================= launch =================
extern "C" void kernel_launch(void* const* d_in, const int* in_sizes, int n_in,
                              void* d_out, int out_size) {
    const float* node_features = (const float*)d_in[0];
    const int*   edge_index    = (const int*)d_in[1];
    const float* pre_w1 = (const float*)d_in[2];
    const float* pre_b1 = (const float*)d_in[3];
    const float* pre_w2 = (const float*)d_in[4];
    const float* pre_b2 = (const float*)d_in[5];
    const float* skip   = (const float*)d_in[6];
    const float* wl[3] = {(const float*)d_in[7], (const float*)d_in[10], (const float*)d_in[13]};
    const float* bl[3] = {(const float*)d_in[8], (const float*)d_in[11], (const float*)d_in[14]};
    const float* wr[3] = {(const float*)d_in[9], (const float*)d_in[12], (const float*)d_in[15]};
    const float* post_w1 = (const float*)d_in[16];
    const float* post_b1 = (const float*)d_in[17];
    const float* post_w2 = (const float*)d_in[18];
    const float* post_b2 = (const float*)d_in[19];
    const float* post_w3 = (const float*)d_in[20];
    const float* post_b3 = (const float*)d_in[21];
    const float* post_w4 = (const float*)d_in[22];
    const float* post_b4 = (const float*)d_in[23];
    float* out = (float*)d_out;

    uint32_t *p_embp, *p_yb;
    unsigned short* p_Bp;
    cudaGetSymbolAddress((void**)&p_embp, g_embp);
    cudaGetSymbolAddress((void**)&p_yb, g_yb);
    cudaGetSymbolAddress((void**)&p_Bp, g_Bp);

    const int NB = (NN + 255) / 256;  // 196
    const int MB = (NN + 127) / 128;  // 391

    cudaStream_t s2;
    cudaStreamCreateWithFlags(&s2, cudaStreamNonBlocking);
    cudaEvent_t eFork, eJoin;
    cudaEventCreateWithFlags(&eFork, cudaEventDisableTiming);
    cudaEventCreateWithFlags(&eJoin, cudaEventDisableTiming);

    cudaEventRecord(eFork, 0);
    cudaStreamWaitEvent(s2, eFork, 0);

    // --- side stream: CSR build (independent of pre-MLP pipeline) ---
    zero_kernel<<<NB, 256, 0, s2>>>();
    hist2_kernel<<<(EE / 2 + 255) / 256, 256, 0, s2>>>(edge_index);
    part_kernel<<<NB, 256, 0, s2>>>();
    fill2_kernel<<<NB, 256, 0, s2>>>(NB);
    scatter2_kernel<<<(EE / 2 + 255) / 256, 256, 0, s2>>>(edge_index);
    cudaEventRecord(eJoin, s2);

    // --- main stream: pack + fused pre-MLP + L0 ---
    packAll_kernel<<<(61440 + 255) / 256, 256>>>(pre_w1, pre_w2, wl[0], wr[0], wl[1], wr[1],
                                                 wl[2], wr[2], skip);
    fused_pre_kernel<<<MB, 256>>>(
        node_features, (const uint4*)(p_Bp), pre_b1,
        (const uint4*)(p_Bp + 16384), pre_b2,
        (const uint4*)(p_Bp + 24576), p_embp, p_yb, NN);

    // join: agg needs the CSR
    cudaStreamWaitEvent(0, eJoin, 0);
    agg_kernel<<<(NN / 2 * 32 + 255) / 256, 256>>>(bl[0], 32);

    mma_gemm6<128><<<MB, 256>>>(p_embp, 128, 128, (const uint4*)(p_Bp + 40960),
                                p_yb, 64, NN);
    agg_kernel<<<(NN / 2 * 32 + 255) / 256, 256>>>(bl[1], 64);

    mma_gemm6<128><<<MB, 256>>>(p_embp, 128, 192, (const uint4*)(p_Bp + 73728),
                                p_yb, 64, NN);
    agg_kernel<<<(NN / 2 * 32 + 255) / 256, 256>>>(bl[2], 96);

    colsum_kernel<<<256, 128>>>();
    post_kernel<<<1, 256>>>(post_w1, post_b1, post_w2, post_b2, post_w3, post_b3,
                            post_w4, post_b4, out);

    cudaEventDestroy(eFork);
    cudaEventDestroy(eJoin);
    cudaStreamDestroy(s2);
}

// round 15
// speedup vs baseline: 2.3301x; 1.0235x over previous
#include <cuda_runtime.h>
#include <cuda_bf16.h>
#include <math.h>
#include <stdint.h>

#define NN 50000
#define EE 800000

// ================= scratch (device globals) =================
__device__ uint32_t g_embp[(size_t)NN * 128];  // [x|h1|h2|h3] packed bf16x2 (2 cols/u32)
__device__ uint32_t g_yb[(size_t)NN * 64];     // per-layer [y | r] packed bf16x2
// packed hi/lo weight images, uint4 frags [bh0,bh1,bl0,bl1] (ushort units):
//  pre1@0 (128x64), pre2@16384 (64x64), L0@24576 (64x128), L1@40960 (128x128), L2@73728 (192x128)
__device__ __align__(16) unsigned short g_Bp[122880];
__device__ int   g_cnt[NN];
__device__ int   g_rowptr[NN];
__device__ int   g_cursor[NN];
__device__ int   g_csr_src[EE];
__device__ float g_invdeg[NN];
__device__ int   g_part[256];
__device__ float g_s[256];

__device__ __forceinline__ uint32_t packbf(float x, float y) {
    return ((uint32_t)__bfloat16_as_ushort(__float2bfloat16(y)) << 16) |
           __bfloat16_as_ushort(__float2bfloat16(x));
}
__device__ __forceinline__ float bflo(uint32_t v) { return __uint_as_float(v << 16); }
__device__ __forceinline__ float bfhi(uint32_t v) { return __uint_as_float(v & 0xFFFF0000u); }

// ================= CSR build =================
__global__ void zero_kernel() {
    int i = blockIdx.x * blockDim.x + threadIdx.x;
    if (i < NN) g_cnt[i] = 0;
    if (i < 256) g_s[i] = 0.f;
}
__global__ void hist2_kernel(const int* __restrict__ ei) {
    int e = (blockIdx.x * blockDim.x + threadIdx.x) * 2;
    if (e < EE) {
        int2 d = *(const int2*)&ei[EE + e];
        atomicAdd(&g_cnt[d.x], 1);
        atomicAdd(&g_cnt[d.y], 1);
    }
}
__global__ void part_kernel() {
    __shared__ int s[256];
    int t = threadIdx.x, b = blockIdx.x;
    int i = b * 256 + t;
    int v = (i < NN) ? g_cnt[i] : 0;
    s[t] = v;
    __syncthreads();
    for (int off = 128; off > 0; off >>= 1) {
        if (t < off) s[t] += s[t + off];
        __syncthreads();
    }
    if (t == 0) g_part[b] = s[0];
}
__global__ void fill2_kernel(int nb) {
    __shared__ int sp[256];
    __shared__ int sl[256];
    int t = threadIdx.x, b = blockIdx.x;
    sp[t] = (t < nb) ? g_part[t] : 0;
    __syncthreads();
    for (int off = 1; off < 256; off <<= 1) {
        int a = (t >= off) ? sp[t - off] : 0;
        __syncthreads();
        sp[t] += a;
        __syncthreads();
    }
    int blockbase = (b == 0) ? 0 : sp[b - 1];
    int i = b * 256 + t;
    int v = (i < NN) ? g_cnt[i] : 0;
    sl[t] = v;
    __syncthreads();
    for (int off = 1; off < 256; off <<= 1) {
        int a = (t >= off) ? sl[t - off] : 0;
        __syncthreads();
        sl[t] += a;
        __syncthreads();
    }
    if (i < NN) {
        int base = blockbase + sl[t] - v;
        g_rowptr[i] = base;
        g_cursor[i] = base;
        g_invdeg[i] = 1.0f / (float)(v > 1 ? v : 1);
    }
}
__global__ void scatter2_kernel(const int* __restrict__ ei) {
    int e = (blockIdx.x * blockDim.x + threadIdx.x) * 2;
    if (e < EE) {
        int2 s = *(const int2*)&ei[e];
        int2 d = *(const int2*)&ei[EE + e];
        int p0 = atomicAdd(&g_cursor[d.x], 1);
        g_csr_src[p0] = s.x;
        int p1 = atomicAdd(&g_cursor[d.y], 1);
        g_csr_src[p1] = s.y;
    }
}

// ================= pack ALL weight images (hi/lo uint4 frags) =================
__device__ __forceinline__ void pack_one(float w, int k, int n, int NTILE, int off_us) {
    int kc = k >> 4, kin = k & 15, nc = n >> 3, nin = n & 7;
    int lane = nin * 4 + ((kin & 7) >> 1);
    int reg = kin >> 3, half = kin & 1;
    int base = ((kc * (NTILE >> 3) + nc) * 32 + lane) * 4;
    __nv_bfloat16 hi = __float2bfloat16(w);
    __nv_bfloat16 lo = __float2bfloat16(w - __bfloat162float(hi));
    g_Bp[off_us + (base + reg) * 2 + half]     = __bfloat16_as_ushort(hi);
    g_Bp[off_us + (base + 2 + reg) * 2 + half] = __bfloat16_as_ushort(lo);
}
__global__ void packAll_kernel(const float* __restrict__ pre_w1, const float* __restrict__ pre_w2,
                               const float* __restrict__ wl0, const float* __restrict__ wr0,
                               const float* __restrict__ wl1, const float* __restrict__ wr1,
                               const float* __restrict__ wl2, const float* __restrict__ wr2,
                               const float* __restrict__ skip) {
    int idx = blockIdx.x * blockDim.x + threadIdx.x;
    if (idx < 8192) {
        int k = idx >> 6, n = idx & 63;
        pack_one(pre_w1[k * 64 + n], k, n, 64, 0);
    } else if (idx < 12288) {
        int j = idx - 8192;
        int k = j >> 6, n = j & 63;
        pack_one(pre_w2[k * 64 + n], k, n, 64, 16384);
    } else if (idx < 20480) {
        int j = idx - 12288;
        int k = j >> 7, n = j & 127;
        float g = 1.f / (1.f + expf(-skip[0]));
        float w = ((n < 64) ? wl0[k * 64 + n] : wr0[k * 64 + (n - 64)]) * g;
        pack_one(w, k, n, 128, 24576);
    } else if (idx < 36864) {
        int j = idx - 20480;
        int k = j >> 7, n = j & 127;
        float g = 1.f / (1.f + expf(-skip[3 + (k >> 6)]));
        float w = ((n < 64) ? wl1[k * 64 + n] : wr1[k * 64 + (n - 64)]) * g;
        pack_one(w, k, n, 128, 40960);
    } else if (idx < 61440) {
        int j = idx - 36864;
        int k = j >> 7, n = j & 127;
        float g = 1.f / (1.f + expf(-skip[6 + (k >> 6)]));
        float w = ((n < 64) ? wl2[k * 64 + n] : wr2[k * 64 + (n - 64)]) * g;
        pack_one(w, k, n, 128, 73728);
    }
}

// ================= HMMA helper =================
__device__ __forceinline__ void mma16816(float* acc, const uint32_t* a,
                                         uint32_t b0, uint32_t b1) {
    asm volatile(
        "mma.sync.aligned.m16n8k16.row.col.f32.bf16.bf16.f32 "
        "{%0,%1,%2,%3}, {%4,%5,%6,%7}, {%8,%9}, {%0,%1,%2,%3};"
        : "+f"(acc[0]), "+f"(acc[1]), "+f"(acc[2]), "+f"(acc[3])
        : "r"(a[0]), "r"(a[1]), "r"(a[2]), "r"(a[3]), "r"(b0), "r"(b1));
}

#define SMS 33  // smem row stride in u32 (32 data + 1 pad)

// ================= fused pre-MLP + L0 GEMM (bf16 A, split W) =================
__global__ void __launch_bounds__(256) fused_pre_kernel(
    const float* __restrict__ X,
    const uint4* __restrict__ B1, const float* __restrict__ b1v,
    const uint4* __restrict__ B2, const float* __restrict__ b2v,
    const uint4* __restrict__ B0,
    uint32_t* __restrict__ embp, uint32_t* __restrict__ yb, int M) {
    __shared__ uint32_t t_s[128 * SMS];
    __shared__ uint32_t x_s[128 * SMS];
    const int tid = threadIdx.x;
    const int wid = tid >> 5, lane = tid & 31;
    const int wm = wid >> 1, wn = wid & 1;
    const int q = lane & 3, tq = lane >> 2;
    const int lr0 = wm * 32 + tq;
    const int gb = blockIdx.x * 128;

    // ---------- phase 1: t = relu(X@W1+b1), K=128, N=64 ----------
    {
        float acc[2][4][4];
#pragma unroll
        for (int m = 0; m < 2; m++)
#pragma unroll
            for (int i = 0; i < 4; i++)
#pragma unroll
                for (int j = 0; j < 4; j++) acc[m][i][j] = 0.f;
        for (int kc = 0; kc < 8; kc++) {
            const int c0 = kc * 16 + 2 * q;
            uint32_t a[2][4];
#pragma unroll
            for (int mf = 0; mf < 2; mf++) {
                int ra = gb + lr0 + mf * 16, rc = ra + 8;
                float2 v00 = make_float2(0.f, 0.f), v01 = v00, v10 = v00, v11 = v00;
                if (ra < M) {
                    v00 = *(const float2*)&X[(size_t)ra * 128 + c0];
                    v01 = *(const float2*)&X[(size_t)ra * 128 + c0 + 8];
                }
                if (rc < M) {
                    v10 = *(const float2*)&X[(size_t)rc * 128 + c0];
                    v11 = *(const float2*)&X[(size_t)rc * 128 + c0 + 8];
                }
                a[mf][0] = packbf(v00.x, v00.y);
                a[mf][1] = packbf(v10.x, v10.y);
                a[mf][2] = packbf(v01.x, v01.y);
                a[mf][3] = packbf(v11.x, v11.y);
            }
            const uint4* bp = B1 + (size_t)(kc * 8 + wn * 4) * 32 + lane;
#pragma unroll
            for (int nc = 0; nc < 4; nc++) {
                uint4 b = bp[nc * 32];
                mma16816(acc[0][nc], a[0], b.x, b.y);
                mma16816(acc[0][nc], a[0], b.z, b.w);
                mma16816(acc[1][nc], a[1], b.x, b.y);
                mma16816(acc[1][nc], a[1], b.z, b.w);
            }
        }
#pragma unroll
        for (int nc = 0; nc < 4; nc++) {
            int col = wn * 32 + nc * 8 + 2 * q;
            float bb0 = b1v[col], bb1 = b1v[col + 1];
#pragma unroll
            for (int mf = 0; mf < 2; mf++) {
                int la = lr0 + mf * 16, lc = la + 8;
                t_s[la * SMS + (col >> 1)] =
                    packbf(fmaxf(acc[mf][nc][0] + bb0, 0.f), fmaxf(acc[mf][nc][1] + bb1, 0.f));
                t_s[lc * SMS + (col >> 1)] =
                    packbf(fmaxf(acc[mf][nc][2] + bb0, 0.f), fmaxf(acc[mf][nc][3] + bb1, 0.f));
            }
        }
    }
    __syncthreads();

    // ---------- phase 2: x = t@W2+b2, K=64, N=64 ----------
    {
        float acc[2][4][4];
#pragma unroll
        for (int m = 0; m < 2; m++)
#pragma unroll
            for (int i = 0; i < 4; i++)
#pragma unroll
                for (int j = 0; j < 4; j++) acc[m][i][j] = 0.f;
        for (int kc = 0; kc < 4; kc++) {
            const int ci = kc * 8 + q;
            uint32_t a[2][4];
#pragma unroll
            for (int mf = 0; mf < 2; mf++) {
                int la = lr0 + mf * 16, lc = la + 8;
                a[mf][0] = t_s[la * SMS + ci];
                a[mf][1] = t_s[lc * SMS + ci];
                a[mf][2] = t_s[la * SMS + ci + 4];
                a[mf][3] = t_s[lc * SMS + ci + 4];
            }
            const uint4* bp = B2 + (size_t)(kc * 8 + wn * 4) * 32 + lane;
#pragma unroll
            for (int nc = 0; nc < 4; nc++) {
                uint4 b = bp[nc * 32];
                mma16816(acc[0][nc], a[0], b.x, b.y);
                mma16816(acc[0][nc], a[0], b.z, b.w);
                mma16816(acc[1][nc], a[1], b.x, b.y);
                mma16816(acc[1][nc], a[1], b.z, b.w);
            }
        }
        __syncthreads();
#pragma unroll
        for (int nc = 0; nc < 4; nc++) {
            int col = wn * 32 + nc * 8 + 2 * q;
            float bb0 = b2v[col], bb1 = b2v[col + 1];
#pragma unroll
            for (int mf = 0; mf < 2; mf++) {
                int la = lr0 + mf * 16, lc = la + 8;
                uint32_t p0 = packbf(acc[mf][nc][0] + bb0, acc[mf][nc][1] + bb1);
                uint32_t p1 = packbf(acc[mf][nc][2] + bb0, acc[mf][nc][3] + bb1);
                x_s[la * SMS + (col >> 1)] = p0;
                if (gb + la < M) embp[(size_t)(gb + la) * 128 + (col >> 1)] = p0;
                x_s[lc * SMS + (col >> 1)] = p1;
                if (gb + lc < M) embp[(size_t)(gb + lc) * 128 + (col >> 1)] = p1;
            }
        }
    }
    __syncthreads();

    // ---------- phase 3: y0|r0 = x@W0g, K=64, N=128 ----------
    {
        float acc[2][8][4];
#pragma unroll
        for (int m = 0; m < 2; m++)
#pragma unroll
            for (int i = 0; i < 8; i++)
#pragma unroll
                for (int j = 0; j < 4; j++) acc[m][i][j] = 0.f;
        for (int kc = 0; kc < 4; kc++) {
            const int ci = kc * 8 + q;
            uint32_t a[2][4];
#pragma unroll
            for (int mf = 0; mf < 2; mf++) {
                int la = lr0 + mf * 16, lc = la + 8;
                a[mf][0] = x_s[la * SMS + ci];
                a[mf][1] = x_s[lc * SMS + ci];
                a[mf][2] = x_s[la * SMS + ci + 4];
                a[mf][3] = x_s[lc * SMS + ci + 4];
            }
            const uint4* bp = B0 + (size_t)(kc * 16 + wn * 8) * 32 + lane;
#pragma unroll
            for (int nc = 0; nc < 8; nc++) {
                uint4 b = bp[nc * 32];
                mma16816(acc[0][nc], a[0], b.x, b.y);
                mma16816(acc[0][nc], a[0], b.z, b.w);
                mma16816(acc[1][nc], a[1], b.x, b.y);
                mma16816(acc[1][nc], a[1], b.z, b.w);
            }
        }
#pragma unroll
        for (int nc = 0; nc < 8; nc++) {
            int col = wn * 64 + nc * 8 + 2 * q;
#pragma unroll
            for (int mf = 0; mf < 2; mf++) {
                int ra = gb + lr0 + mf * 16, rc = ra + 8;
                if (ra < M) yb[(size_t)ra * 64 + (col >> 1)] =
                    packbf(acc[mf][nc][0], acc[mf][nc][1]);
                if (rc < M) yb[(size_t)rc * 64 + (col >> 1)] =
                    packbf(acc[mf][nc][2], acc[mf][nc][3]);
            }
        }
    }
}

// ================= standalone GEMM (layers 1,2): bf16 A, split W ====
template <int NTILE>
__global__ void __launch_bounds__(256) mma_gemm6(
    const uint32_t* __restrict__ Ap, int lda, int K,
    const uint4* __restrict__ Bp,
    uint32_t* __restrict__ Cout, int ldc, int M) {
    constexpr int NFRAG = NTILE / 8;
    constexpr int WNF = NFRAG / 2;
    const int tid = threadIdx.x;
    const int wid = tid >> 5, lane = tid & 31;
    const int wm = wid >> 1, wn = wid & 1;
    const int q = lane & 3, tq = lane >> 2;
    const int rb = blockIdx.x * 128 + wm * 32 + tq;

    float acc[2][WNF][4];
#pragma unroll
    for (int m = 0; m < 2; m++)
#pragma unroll
        for (int i = 0; i < WNF; i++)
#pragma unroll
            for (int j = 0; j < 4; j++) acc[m][i][j] = 0.f;

    for (int kc = 0; kc < K / 16; kc++) {
        const int ci = kc * 8 + q;
        uint32_t a[2][4];
#pragma unroll
        for (int mf = 0; mf < 2; mf++) {
            int ra = rb + mf * 16, rc = ra + 8;
            uint32_t a0 = 0, a1 = 0, a2 = 0, a3 = 0;
            if (ra < M) {
                a0 = Ap[(size_t)ra * lda + ci];
                a2 = Ap[(size_t)ra * lda + ci + 4];
            }
            if (rc < M) {
                a1 = Ap[(size_t)rc * lda + ci];
                a3 = Ap[(size_t)rc * lda + ci + 4];
            }
            a[mf][0] = a0; a[mf][1] = a1; a[mf][2] = a2; a[mf][3] = a3;
        }
        const uint4* bp = Bp + (size_t)(kc * NFRAG + wn * WNF) * 32 + lane;
#pragma unroll
        for (int nc = 0; nc < WNF; nc++) {
            uint4 b = bp[nc * 32];
            mma16816(acc[0][nc], a[0], b.x, b.y);
            mma16816(acc[0][nc], a[0], b.z, b.w);
            mma16816(acc[1][nc], a[1], b.x, b.y);
            mma16816(acc[1][nc], a[1], b.z, b.w);
        }
    }

#pragma unroll
    for (int nc = 0; nc < WNF; nc++) {
        int col = wn * (NTILE / 2) + nc * 8 + 2 * q;
#pragma unroll
        for (int mf = 0; mf < 2; mf++) {
            int ra = rb + mf * 16, rc = ra + 8;
            if (ra < M) Cout[(size_t)ra * ldc + (col >> 1)] =
                packbf(acc[mf][nc][0], acc[mf][nc][1]);
            if (rc < M) Cout[(size_t)rc * ldc + (col >> 1)] =
                packbf(acc[mf][nc][2], acc[mf][nc][3]);
        }
    }
}

// ================= aggregation: 4 nodes per warp, 8 lanes/node, uint4 ==========
__global__ void agg_kernel(const float* __restrict__ bl, int outc) {
    int gw = (blockIdx.x * blockDim.x + threadIdx.x) >> 5;
    int lane = threadIdx.x & 31;
    int quad = lane >> 3;      // which node within the warp (0..3)
    int h = lane & 7;          // lane within node: covers u32 cols 4h..4h+3
    int n = gw * 4 + quad;
    if (n >= NN) return;
    const int beg = g_rowptr[n], cnt = g_cnt[n];
    const uint32_t* __restrict__ yb = g_yb;
    float s0 = 0.f, s1 = 0.f, s2 = 0.f, s3 = 0.f;
    float s4 = 0.f, s5 = 0.f, s6 = 0.f, s7 = 0.f;
    for (int k = 0; k < cnt; k++) {
        int src = g_csr_src[beg + k];
        uint4 v = *(const uint4*)&yb[(size_t)src * 64 + 4 * h];
        s0 += bflo(v.x); s1 += bfhi(v.x);
        s2 += bflo(v.y); s3 += bfhi(v.y);
        s4 += bflo(v.z); s5 += bfhi(v.z);
        s6 += bflo(v.w); s7 += bfhi(v.w);
    }
    float inv = g_invdeg[n];
    uint4 rv = *(const uint4*)&yb[(size_t)n * 64 + 32 + 4 * h];
    float h0 = fmaxf(s0 * inv + bl[8 * h]     + bflo(rv.x), 0.f);
    float h1 = fmaxf(s1 * inv + bl[8 * h + 1] + bfhi(rv.x), 0.f);
    float h2 = fmaxf(s2 * inv + bl[8 * h + 2] + bflo(rv.y), 0.f);
    float h3 = fmaxf(s3 * inv + bl[8 * h + 3] + bfhi(rv.y), 0.f);
    float h4 = fmaxf(s4 * inv + bl[8 * h + 4] + bflo(rv.z), 0.f);
    float h5 = fmaxf(s5 * inv + bl[8 * h + 5] + bfhi(rv.z), 0.f);
    float h6 = fmaxf(s6 * inv + bl[8 * h + 6] + bflo(rv.w), 0.f);
    float h7 = fmaxf(s7 * inv + bl[8 * h + 7] + bfhi(rv.w), 0.f);
    uint4 o;
    o.x = packbf(h0, h1);
    o.y = packbf(h2, h3);
    o.z = packbf(h4, h5);
    o.w = packbf(h6, h7);
    *(uint4*)&g_embp[(size_t)n * 128 + outc + 4 * h] = o;
}

// ================= column sum over packed emb + post mlp =================
__global__ void colsum_kernel() {
    int t = threadIdx.x;  // 128 threads: col pair (2t, 2t+1)
    int per = (NN + gridDim.x - 1) / gridDim.x;
    int n0 = blockIdx.x * per;
    int n1 = n0 + per;
    if (n1 > NN) n1 = NN;
    float s0 = 0.f, s1 = 0.f;
    for (int n = n0; n < n1; n++) {
        uint32_t w = g_embp[(size_t)n * 128 + t];
        s0 += bflo(w);
        s1 += bfhi(w);
    }
    atomicAdd(&g_s[2 * t], s0);
    atomicAdd(&g_s[2 * t + 1], s1);
}
__global__ void post_kernel(const float* __restrict__ w1, const float* __restrict__ b1,
                            const float* __restrict__ w2, const float* __restrict__ b2,
                            const float* __restrict__ w3, const float* __restrict__ b3,
                            const float* __restrict__ w4, const float* __restrict__ b4,
                            float* __restrict__ out) {
    __shared__ float s1[64], s2[64], s3[256];
    int t = threadIdx.x;
    if (t < 64) {
        float a = b1[t];
        for (int k = 0; k < 256; k++) a += g_s[k] * w1[k * 64 + t];
        s1[t] = (a > 0.f) ? a : 0.1f * a;
    }
    __syncthreads();
    if (t < 64) {
        float a = b2[t];
        for (int k = 0; k < 64; k++) a += s1[k] * w2[k * 64 + t];
        s2[t] = fmaxf(a, 0.f);
    }
    __syncthreads();
    {
        float a = b3[t];
        for (int k = 0; k < 64; k++) a += s2[k] * w3[k * 256 + t];
        s3[t] = fmaxf(a, 0.f);
    }
    __syncthreads();
    if (t < 64) {
        float a = b4[t];
        for (int k = 0; k < 256; k++) a += s3[k] * w4[k * 64 + t];
        out[t] = a;
    }
}

// ================= launch =================
extern "C" void kernel_launch(void* const* d_in, const int* in_sizes, int n_in,
                              void* d_out, int out_size) {
    const float* node_features = (const float*)d_in[0];
    const int*   edge_index    = (const int*)d_in[1];
    const float* pre_w1 = (const float*)d_in[2];
    const float* pre_b1 = (const float*)d_in[3];
    const float* pre_w2 = (const float*)d_in[4];
    const float* pre_b2 = (const float*)d_in[5];
    const float* skip   = (const float*)d_in[6];
    const float* wl[3] = {(const float*)d_in[7], (const float*)d_in[10], (const float*)d_in[13]};
    const float* bl[3] = {(const float*)d_in[8], (const float*)d_in[11], (const float*)d_in[14]};
    const float* wr[3] = {(const float*)d_in[9], (const float*)d_in[12], (const float*)d_in[15]};
    const float* post_w1 = (const float*)d_in[16];
    const float* post_b1 = (const float*)d_in[17];
    const float* post_w2 = (const float*)d_in[18];
    const float* post_b2 = (const float*)d_in[19];
    const float* post_w3 = (const float*)d_in[20];
    const float* post_b3 = (const float*)d_in[21];
    const float* post_w4 = (const float*)d_in[22];
    const float* post_b4 = (const float*)d_in[23];
    float* out = (float*)d_out;

    uint32_t *p_embp, *p_yb;
    unsigned short* p_Bp;
    cudaGetSymbolAddress((void**)&p_embp, g_embp);
    cudaGetSymbolAddress((void**)&p_yb, g_yb);
    cudaGetSymbolAddress((void**)&p_Bp, g_Bp);

    const int NB = (NN + 255) / 256;  // 196
    const int MB = (NN + 127) / 128;  // 391
    const int AGGB = (NN / 4 * 32 + 255) / 256;  // 12500 warps -> 1563 blocks

    cudaStream_t s2;
    cudaStreamCreateWithFlags(&s2, cudaStreamNonBlocking);
    cudaEvent_t eFork, eJoin;
    cudaEventCreateWithFlags(&eFork, cudaEventDisableTiming);
    cudaEventCreateWithFlags(&eJoin, cudaEventDisableTiming);

    cudaEventRecord(eFork, 0);
    cudaStreamWaitEvent(s2, eFork, 0);

    // --- side stream: CSR build (independent of pre-MLP pipeline) ---
    zero_kernel<<<NB, 256, 0, s2>>>();
    hist2_kernel<<<(EE / 2 + 255) / 256, 256, 0, s2>>>(edge_index);
    part_kernel<<<NB, 256, 0, s2>>>();
    fill2_kernel<<<NB, 256, 0, s2>>>(NB);
    scatter2_kernel<<<(EE / 2 + 255) / 256, 256, 0, s2>>>(edge_index);
    cudaEventRecord(eJoin, s2);

    // --- main stream: pack + fused pre-MLP + L0 ---
    packAll_kernel<<<(61440 + 255) / 256, 256>>>(pre_w1, pre_w2, wl[0], wr[0], wl[1], wr[1],
                                                 wl[2], wr[2], skip);
    fused_pre_kernel<<<MB, 256>>>(
        node_features, (const uint4*)(p_Bp), pre_b1,
        (const uint4*)(p_Bp + 16384), pre_b2,
        (const uint4*)(p_Bp + 24576), p_embp, p_yb, NN);

    // join: agg needs the CSR
    cudaStreamWaitEvent(0, eJoin, 0);
    agg_kernel<<<AGGB, 256>>>(bl[0], 32);

    mma_gemm6<128><<<MB, 256>>>(p_embp, 128, 128, (const uint4*)(p_Bp + 40960),
                                p_yb, 64, NN);
    agg_kernel<<<AGGB, 256>>>(bl[1], 64);

    mma_gemm6<128><<<MB, 256>>>(p_embp, 128, 192, (const uint4*)(p_Bp + 73728),
                                p_yb, 64, NN);
    agg_kernel<<<AGGB, 256>>>(bl[2], 96);

    colsum_kernel<<<256, 128>>>();
    post_kernel<<<1, 256>>>(post_w1, post_b1, post_w2, post_b2, post_w3, post_b3,
                            post_w4, post_b4, out);

    cudaEventDestroy(eFork);
    cudaEventDestroy(eJoin);
    cudaStreamDestroy(s2);
}